// round 1
// baseline (speedup 1.0000x reference)
#include <cuda_runtime.h>
#include <cuda_bf16.h>
#include <math.h>

#define BATCH 4
#define SEQ   4096
#define EMB   1024
#define HEAD  64
#define NPROJ 192   // 3*HEAD concatenated outputs (q|k|v)

// Scratch for projected q, k, v  (each 4*4096*64 floats = 4 MB)
__device__ float g_q[BATCH * SEQ * HEAD];
__device__ float g_k[BATCH * SEQ * HEAD];
__device__ float g_v[BATCH * SEQ * HEAD];

// ---------------------------------------------------------------------------
// Kernel 1: fused QKV projection.
// C[M=16384, N=192] = x[M, K=1024] @ [Wq|Wk|Wv][K, 192] + bias
// Block tile: 64 rows x 192 cols, K-chunk 32. Threads: 16x16.
// Per-thread microtile: 4 rows x 12 cols.
// ---------------------------------------------------------------------------
__global__ __launch_bounds__(256) void qkv_kernel(
    const float* __restrict__ x,
    const float* __restrict__ Wq, const float* __restrict__ bq,
    const float* __restrict__ Wk, const float* __restrict__ bk,
    const float* __restrict__ Wv, const float* __restrict__ bv)
{
    __shared__ float xs[64][33];    // [m][k], padded
    __shared__ float ws[32][192];   // [k][c]

    const int tx  = threadIdx.x;    // 0..15 -> 12 cols each
    const int ty  = threadIdx.y;    // 0..15 -> 4 rows each
    const int tid = ty * 16 + tx;
    const int row0 = blockIdx.x * 64;

    float acc[4][12];
#pragma unroll
    for (int i = 0; i < 4; i++)
#pragma unroll
        for (int j = 0; j < 12; j++) acc[i][j] = 0.0f;

    for (int k0 = 0; k0 < EMB; k0 += 32) {
        // load x tile: 64 rows x 32 k (two float4 per thread)
        {
            const int m  = tid >> 2;          // 0..63
            const int ko = (tid & 3) * 8;     // 0,8,16,24
            const float4* src =
                reinterpret_cast<const float4*>(x + (size_t)(row0 + m) * EMB + k0 + ko);
            float4 v0 = src[0];
            float4 v1 = src[1];
            xs[m][ko + 0] = v0.x; xs[m][ko + 1] = v0.y;
            xs[m][ko + 2] = v0.z; xs[m][ko + 3] = v0.w;
            xs[m][ko + 4] = v1.x; xs[m][ko + 5] = v1.y;
            xs[m][ko + 6] = v1.z; xs[m][ko + 7] = v1.w;
        }
        // load W tile: 32 k x 192 c
        for (int i = tid; i < 32 * NPROJ; i += 256) {
            const int k = i / NPROJ;
            const int c = i % NPROJ;
            float w;
            if (c < 64)       w = Wq[(k0 + k) * HEAD + c];
            else if (c < 128) w = Wk[(k0 + k) * HEAD + (c - 64)];
            else              w = Wv[(k0 + k) * HEAD + (c - 128)];
            ws[k][c] = w;
        }
        __syncthreads();

#pragma unroll
        for (int k = 0; k < 32; k++) {
            float a[4], b[12];
#pragma unroll
            for (int i = 0; i < 4; i++)  a[i] = xs[ty * 4 + i][k];
#pragma unroll
            for (int j = 0; j < 12; j++) b[j] = ws[k][tx * 12 + j];
#pragma unroll
            for (int i = 0; i < 4; i++)
#pragma unroll
                for (int j = 0; j < 12; j++)
                    acc[i][j] = fmaf(a[i], b[j], acc[i][j]);
        }
        __syncthreads();
    }

    // epilogue: add bias, scatter to g_q / g_k / g_v
#pragma unroll
    for (int i = 0; i < 4; i++) {
        const int r = row0 + ty * 4 + i;
#pragma unroll
        for (int j = 0; j < 12; j++) {
            const int c = tx * 12 + j;
            if (c < 64)       g_q[(size_t)r * HEAD + c]         = acc[i][j] + bq[c];
            else if (c < 128) g_k[(size_t)r * HEAD + (c - 64)]  = acc[i][j] + bk[c - 64];
            else              g_v[(size_t)r * HEAD + (c - 128)] = acc[i][j] + bv[c - 128];
        }
    }
}

// ---------------------------------------------------------------------------
// Kernel 2: causal flash attention. One block per (batch, q-tile of 64).
// BQ = BK = 64, HEAD = 64. 256 threads = 8 warps.
// Score phase: 16x16 thread grid, 4x4 microtile.
// Softmax/AV phase: warp w owns queries w*8..w*8+7; lane owns cols lane, lane+32.
// ---------------------------------------------------------------------------
#define LDP 65   // padded row stride (floats) to avoid bank conflicts

__global__ __launch_bounds__(256) void attn_kernel(float* __restrict__ out)
{
    extern __shared__ float sm[];
    float* Qs = sm;                 // 64 * LDP
    float* Ks = Qs + 64 * LDP;
    float* Vs = Ks + 64 * LDP;
    float* Sc = Vs + 64 * LDP;

    const int b   = blockIdx.y;
    const int qt  = blockIdx.x;     // q-tile index 0..63
    const int tid = threadIdx.x;
    const int tx  = tid & 15;
    const int ty  = tid >> 4;
    const int warp = tid >> 5;
    const int lane = tid & 31;
    const int qb   = warp * 8;      // first query row this warp owns

    // load Q tile, folding in 1/sqrt(H) = 0.125
    {
        const float* qp = g_q + ((size_t)(b * SEQ) + qt * 64) * HEAD;
        for (int i = tid; i < 64 * 64; i += 256) {
            const int r = i >> 6, d = i & 63;
            Qs[r * LDP + d] = qp[i] * 0.125f;
        }
    }

    float mrow[8], lrow[8], acc0[8], acc1[8];
#pragma unroll
    for (int q = 0; q < 8; q++) {
        mrow[q] = -1e30f; lrow[q] = 0.0f; acc0[q] = 0.0f; acc1[q] = 0.0f;
    }
    __syncthreads();

    for (int kt = 0; kt <= qt; kt++) {
        // load K, V tiles
        {
            const float* kp = g_k + ((size_t)(b * SEQ) + kt * 64) * HEAD;
            const float* vp = g_v + ((size_t)(b * SEQ) + kt * 64) * HEAD;
            for (int i = tid; i < 64 * 64; i += 256) {
                const int r = i >> 6, d = i & 63;
                Ks[r * LDP + d] = kp[i];
                Vs[r * LDP + d] = vp[i];
            }
        }
        __syncthreads();

        // ---- scores: 4x4 per-thread microtile over [64q x 64k] ----
        float s[4][4];
#pragma unroll
        for (int i = 0; i < 4; i++)
#pragma unroll
            for (int j = 0; j < 4; j++) s[i][j] = 0.0f;

#pragma unroll 8
        for (int d = 0; d < 64; d++) {
            float qv[4], kv[4];
#pragma unroll
            for (int i = 0; i < 4; i++) qv[i] = Qs[(ty * 4 + i) * LDP + d];
#pragma unroll
            for (int j = 0; j < 4; j++) kv[j] = Ks[(tx * 4 + j) * LDP + d];
#pragma unroll
            for (int i = 0; i < 4; i++)
#pragma unroll
                for (int j = 0; j < 4; j++)
                    s[i][j] = fmaf(qv[i], kv[j], s[i][j]);
        }

        const bool diag = (kt == qt);
#pragma unroll
        for (int i = 0; i < 4; i++) {
            const int qi = ty * 4 + i;
#pragma unroll
            for (int j = 0; j < 4; j++) {
                const int ki = tx * 4 + j;
                float v = s[i][j];
                if (diag && ki > qi) v = -1e30f;
                Sc[qi * LDP + ki] = v;
            }
        }
        __syncthreads();

        // ---- online softmax for this warp's 8 query rows ----
#pragma unroll
        for (int q = 0; q < 8; q++) {
            const int row = qb + q;
            float s1 = Sc[row * LDP + lane];
            float s2 = Sc[row * LDP + 32 + lane];
            float tmax = fmaxf(s1, s2);
#pragma unroll
            for (int off = 16; off > 0; off >>= 1)
                tmax = fmaxf(tmax, __shfl_xor_sync(0xffffffffu, tmax, off));
            const float mn = fmaxf(mrow[q], tmax);
            const float p1 = __expf(s1 - mn);
            const float p2 = __expf(s2 - mn);
            float psum = p1 + p2;
#pragma unroll
            for (int off = 16; off > 0; off >>= 1)
                psum += __shfl_xor_sync(0xffffffffu, psum, off);
            const float corr = __expf(mrow[q] - mn);
            lrow[q] = lrow[q] * corr + psum;
            mrow[q] = mn;
            acc0[q] *= corr;
            acc1[q] *= corr;
            Sc[row * LDP + lane]      = p1;
            Sc[row * LDP + 32 + lane] = p2;
        }
        __syncwarp();

        // ---- AV: acc[q][col] += sum_k P[q][k] * V[k][col] ----
#pragma unroll 4
        for (int k = 0; k < 64; k++) {
            const float v1 = Vs[k * LDP + lane];
            const float v2 = Vs[k * LDP + 32 + lane];
#pragma unroll
            for (int q = 0; q < 8; q++) {
                const float p = Sc[(qb + q) * LDP + k];
                acc0[q] = fmaf(p, v1, acc0[q]);
                acc1[q] = fmaf(p, v2, acc1[q]);
            }
        }
        __syncthreads();   // before next tile overwrites Ks/Vs/Sc
    }

    // ---- write output ----
#pragma unroll
    for (int q = 0; q < 8; q++) {
        const int row = qt * 64 + qb + q;
        const float inv = 1.0f / lrow[q];
        float* o = out + ((size_t)(b * SEQ) + row) * HEAD;
        o[lane]      = acc0[q] * inv;
        o[32 + lane] = acc1[q] * inv;
    }
}

// ---------------------------------------------------------------------------
extern "C" void kernel_launch(void* const* d_in, const int* in_sizes, int n_in,
                              void* d_out, int out_size)
{
    const float* x  = (const float*)d_in[0];
    const float* Wq = (const float*)d_in[1];
    const float* bq = (const float*)d_in[2];
    const float* Wk = (const float*)d_in[3];
    const float* bk = (const float*)d_in[4];
    const float* Wv = (const float*)d_in[5];
    const float* bv = (const float*)d_in[6];
    float* out = (float*)d_out;

    // QKV projection: 16384 rows / 64 per block
    {
        dim3 grid(BATCH * SEQ / 64);
        dim3 block(16, 16);
        qkv_kernel<<<grid, block>>>(x, Wq, bq, Wk, bk, Wv, bv);
    }

    // Flash attention
    {
        const int smem = 4 * 64 * LDP * sizeof(float);  // 66560 B
        cudaFuncSetAttribute(attn_kernel,
                             cudaFuncAttributeMaxDynamicSharedMemorySize, smem);
        dim3 grid(SEQ / 64, BATCH);
        attn_kernel<<<grid, 256, smem>>>(out);
    }
}

// round 3
// speedup vs baseline: 1.2456x; 1.2456x over previous
#include <cuda_runtime.h>
#include <cuda_bf16.h>
#include <math.h>
#include <cstdint>

#define BATCH 4
#define SEQ   4096
#define EMB   1024
#define HEAD  64
#define NPROJ 192

// bf16 hi/lo split of projected q (pre-scaled by 0.125), k, v. 2 MB each.
__device__ __nv_bfloat16 g_qhi[BATCH * SEQ * HEAD];
__device__ __nv_bfloat16 g_qlo[BATCH * SEQ * HEAD];
__device__ __nv_bfloat16 g_khi[BATCH * SEQ * HEAD];
__device__ __nv_bfloat16 g_klo[BATCH * SEQ * HEAD];
__device__ __nv_bfloat16 g_vhi[BATCH * SEQ * HEAD];
__device__ __nv_bfloat16 g_vlo[BATCH * SEQ * HEAD];

// ===========================================================================
// helpers
// ===========================================================================
__device__ __forceinline__ uint32_t smem_u32(const void* p) {
    uint32_t a;
    asm("{ .reg .u64 t; cvta.to.shared.u64 t, %1; cvt.u32.u64 %0, t; }"
        : "=r"(a) : "l"(p));
    return a;
}

__device__ __forceinline__ void ldsm4(uint32_t addr, uint32_t* r) {
    asm volatile("ldmatrix.sync.aligned.m8n8.x4.shared.b16 {%0,%1,%2,%3}, [%4];"
        : "=r"(r[0]), "=r"(r[1]), "=r"(r[2]), "=r"(r[3]) : "r"(addr));
}
__device__ __forceinline__ void ldsm4t(uint32_t addr, uint32_t* r) {
    asm volatile("ldmatrix.sync.aligned.m8n8.x4.trans.shared.b16 {%0,%1,%2,%3}, [%4];"
        : "=r"(r[0]), "=r"(r[1]), "=r"(r[2]), "=r"(r[3]) : "r"(addr));
}

// D += A * B   (m16n8k16, bf16 in, f32 accum)
__device__ __forceinline__ void mma16816(float* c, const uint32_t* a,
                                         uint32_t b0, uint32_t b1) {
    asm volatile(
        "mma.sync.aligned.m16n8k16.row.col.f32.bf16.bf16.f32 "
        "{%0,%1,%2,%3}, {%4,%5,%6,%7}, {%8,%9}, {%0,%1,%2,%3};"
        : "+f"(c[0]), "+f"(c[1]), "+f"(c[2]), "+f"(c[3])
        : "r"(a[0]), "r"(a[1]), "r"(a[2]), "r"(a[3]), "r"(b0), "r"(b1));
}

__device__ __forceinline__ uint32_t pack2(__nv_bfloat16 lo, __nv_bfloat16 hi) {
    return (uint32_t)__bfloat16_as_ushort(lo) |
           ((uint32_t)__bfloat16_as_ushort(hi) << 16);
}

// split pair of fp32 into bf16 hi-frag word and lo-frag word
__device__ __forceinline__ void split2(float x0, float x1,
                                       uint32_t& hw, uint32_t& lw) {
    __nv_bfloat16 h0 = __float2bfloat16(x0);
    __nv_bfloat16 h1 = __float2bfloat16(x1);
    float l0 = x0 - __bfloat162float(h0);
    float l1 = x1 - __bfloat162float(h1);
    hw = pack2(h0, h1);
    lw = pack2(__float2bfloat16(l0), __float2bfloat16(l1));
}

// ===========================================================================
// Kernel 1: fused QKV projection (scalar mainloop; hi/lo bf16 epilogue)
// ===========================================================================
__global__ __launch_bounds__(256) void qkv_kernel(
    const float* __restrict__ x,
    const float* __restrict__ Wq, const float* __restrict__ bq,
    const float* __restrict__ Wk, const float* __restrict__ bk,
    const float* __restrict__ Wv, const float* __restrict__ bv)
{
    __shared__ float xs[64][33];
    __shared__ float ws[32][192];

    const int tx  = threadIdx.x;
    const int ty  = threadIdx.y;
    const int tid = ty * 16 + tx;
    const int row0 = blockIdx.x * 64;

    float acc[4][12];
#pragma unroll
    for (int i = 0; i < 4; i++)
#pragma unroll
        for (int j = 0; j < 12; j++) acc[i][j] = 0.0f;

    for (int k0 = 0; k0 < EMB; k0 += 32) {
        {
            const int m  = tid >> 2;
            const int ko = (tid & 3) * 8;
            const float4* src =
                reinterpret_cast<const float4*>(x + (size_t)(row0 + m) * EMB + k0 + ko);
            float4 v0 = src[0];
            float4 v1 = src[1];
            xs[m][ko + 0] = v0.x; xs[m][ko + 1] = v0.y;
            xs[m][ko + 2] = v0.z; xs[m][ko + 3] = v0.w;
            xs[m][ko + 4] = v1.x; xs[m][ko + 5] = v1.y;
            xs[m][ko + 6] = v1.z; xs[m][ko + 7] = v1.w;
        }
        for (int i = tid; i < 32 * NPROJ; i += 256) {
            const int k = i / NPROJ;
            const int c = i % NPROJ;
            float w;
            if (c < 64)       w = Wq[(k0 + k) * HEAD + c];
            else if (c < 128) w = Wk[(k0 + k) * HEAD + (c - 64)];
            else              w = Wv[(k0 + k) * HEAD + (c - 128)];
            ws[k][c] = w;
        }
        __syncthreads();

#pragma unroll
        for (int k = 0; k < 32; k++) {
            float a[4], b[12];
#pragma unroll
            for (int i = 0; i < 4; i++)  a[i] = xs[ty * 4 + i][k];
#pragma unroll
            for (int j = 0; j < 12; j++) b[j] = ws[k][tx * 12 + j];
#pragma unroll
            for (int i = 0; i < 4; i++)
#pragma unroll
                for (int j = 0; j < 12; j++)
                    acc[i][j] = fmaf(a[i], b[j], acc[i][j]);
        }
        __syncthreads();
    }

    // epilogue: bias, fold q-scale, split into bf16 hi/lo, write pairs
#pragma unroll
    for (int i = 0; i < 4; i++) {
        const size_t r = row0 + ty * 4 + i;
#pragma unroll
        for (int j = 0; j < 12; j += 2) {
            const int c = tx * 12 + j;
            float v0 = acc[i][j], v1 = acc[i][j + 1];
            __nv_bfloat16 *hiA, *loA;
            size_t idx;
            if (c < 64) {
                v0 = (v0 + bq[c]) * 0.125f;
                v1 = (v1 + bq[c + 1]) * 0.125f;
                hiA = g_qhi; loA = g_qlo; idx = r * HEAD + c;
            } else if (c < 128) {
                v0 += bk[c - 64]; v1 += bk[c - 63];
                hiA = g_khi; loA = g_klo; idx = r * HEAD + (c - 64);
            } else {
                v0 += bv[c - 128]; v1 += bv[c - 127];
                hiA = g_vhi; loA = g_vlo; idx = r * HEAD + (c - 128);
            }
            __nv_bfloat16 h0 = __float2bfloat16(v0);
            __nv_bfloat16 h1 = __float2bfloat16(v1);
            float l0 = v0 - __bfloat162float(h0);
            float l1 = v1 - __bfloat162float(h1);
            __nv_bfloat162 hh; hh.x = h0; hh.y = h1;
            __nv_bfloat162 ll; ll.x = __float2bfloat16(l0); ll.y = __float2bfloat16(l1);
            *reinterpret_cast<__nv_bfloat162*>(hiA + idx) = hh;
            *reinterpret_cast<__nv_bfloat162*>(loA + idx) = ll;
        }
    }
}

// ===========================================================================
// Kernel 2: flash attention on mma.sync bf16 (3xBF16 emulation).
// BQ=64, BK=64, 128 threads (4 warps, warp w owns q-rows 16w..16w+15).
// ===========================================================================
#define BQ 64
#define BK 64
#define STRIDE 144                         // smem row stride in bytes (72 bf16)

#define SM_QHI 0
#define SM_QLO 9216
#define SM_KHI 18432
#define SM_KLO 27648
#define SM_VHI 36864
#define SM_VLO 46080
#define SM_TOTAL 55296

__global__ __launch_bounds__(128) void attn_mma_kernel(float* __restrict__ out)
{
    extern __shared__ char smem[];
    const uint32_t sbase = smem_u32(smem);

    const int u  = blockIdx.x;
    const int b  = u & 3;
    const int v_ = u >> 2;
    const int qt = (v_ & 1) ? (63 - (v_ >> 1)) : (v_ >> 1);  // long/short interleave
    const int q0 = qt * BQ;
    const int nk = qt + 1;

    const int tid  = threadIdx.x;
    const int warp = tid >> 5;
    const int lane = tid & 31;
    const int g    = lane >> 2;      // row group 0..7
    const int qr   = lane & 3;       // quad 0..3
    const int R    = warp * 16;      // warp's first q-row in tile

    // ---- load Q tile (hi+lo) into smem ----
    for (int i = tid; i < 1024; i += 128) {
        const int arr = i >> 9;           // 0 = hi, 1 = lo
        const int rem = i & 511;
        const int r = rem >> 3, c = rem & 7;
        const __nv_bfloat16* src = (arr == 0 ? g_qhi : g_qlo)
            + ((size_t)(b * SEQ) + q0 + r) * HEAD + c * 8;
        const int4 val = *reinterpret_cast<const int4*>(src);
        *reinterpret_cast<int4*>(smem + (arr == 0 ? SM_QHI : SM_QLO)
                                 + r * STRIDE + c * 16) = val;
    }
    __syncthreads();

    // ---- cache Q A-fragments (4 k-chunks, hi + lo) ----
    const uint32_t aQ = sbase + SM_QHI
        + (uint32_t)(R + (lane & 15)) * STRIDE + ((lane >> 4) * 8) * 2;
    uint32_t qahi[4][4], qalo[4][4];
#pragma unroll
    for (int kc = 0; kc < 4; kc++) {
        ldsm4(aQ + kc * 32, qahi[kc]);
        ldsm4(aQ + 9216 + kc * 32, qalo[kc]);
    }

    // per-lane ldmatrix bases for K (B-frag) and V (trans B-frag)
    const uint32_t bK = sbase + SM_KHI
        + (uint32_t)(((lane >> 4) & 1) * 8 + (lane & 7)) * STRIDE
        + (((lane >> 3) & 1) * 8) * 2;
    const uint32_t bV = sbase + SM_VHI
        + (uint32_t)(((lane >> 3) & 1) * 8 + (lane & 7)) * STRIDE
        + (((lane >> 4) & 1) * 8) * 2;

    float oacc[8][4];
#pragma unroll
    for (int nt = 0; nt < 8; nt++)
#pragma unroll
        for (int e = 0; e < 4; e++) oacc[nt][e] = 0.0f;
    float mr0 = -1e30f, mr1 = -1e30f, l0 = 0.0f, l1 = 0.0f;

    for (int kt = 0; kt < nk; kt++) {
        __syncthreads();   // prev compute done before overwriting K/V
        // ---- load K,V tiles (hi+lo) ----
        for (int i = tid; i < 2048; i += 128) {
            const int arr = i >> 9;       // 0 khi, 1 klo, 2 vhi, 3 vlo
            const int rem = i & 511;
            const int r = rem >> 3, c = rem & 7;
            const __nv_bfloat16* base;
            uint32_t soff;
            if (arr == 0)      { base = g_khi; soff = SM_KHI; }
            else if (arr == 1) { base = g_klo; soff = SM_KLO; }
            else if (arr == 2) { base = g_vhi; soff = SM_VHI; }
            else               { base = g_vlo; soff = SM_VLO; }
            const int4 val = *reinterpret_cast<const int4*>(
                base + ((size_t)(b * SEQ) + kt * BK + r) * HEAD + c * 8);
            *reinterpret_cast<int4*>(smem + soff + r * STRIDE + c * 16) = val;
        }
        __syncthreads();

        // ---- S = Q K^T  (hi*hi + hi*lo + lo*hi) ----
        float sacc[8][4];
#pragma unroll
        for (int nt = 0; nt < 8; nt++)
#pragma unroll
            for (int e = 0; e < 4; e++) sacc[nt][e] = 0.0f;

#pragma unroll
        for (int kc = 0; kc < 4; kc++) {
#pragma unroll
            for (int np = 0; np < 4; np++) {
                uint32_t bh[4], bl[4];
                ldsm4(bK + np * (16 * STRIDE) + kc * 32, bh);
                ldsm4(bK + 9216 + np * (16 * STRIDE) + kc * 32, bl);
                mma16816(sacc[2 * np],     qahi[kc], bh[0], bh[1]);
                mma16816(sacc[2 * np],     qahi[kc], bl[0], bl[1]);
                mma16816(sacc[2 * np],     qalo[kc], bh[0], bh[1]);
                mma16816(sacc[2 * np + 1], qahi[kc], bh[2], bh[3]);
                mma16816(sacc[2 * np + 1], qahi[kc], bl[2], bl[3]);
                mma16816(sacc[2 * np + 1], qalo[kc], bh[2], bh[3]);
            }
        }

        // ---- causal mask (diagonal tile only) ----
        if (kt == qt) {
            const int lr0 = R + g, lr1 = R + g + 8;
#pragma unroll
            for (int nt = 0; nt < 8; nt++) {
                const int lc = nt * 8 + qr * 2;
                if (lc > lr0)     sacc[nt][0] = -1e30f;
                if (lc + 1 > lr0) sacc[nt][1] = -1e30f;
                if (lc > lr1)     sacc[nt][2] = -1e30f;
                if (lc + 1 > lr1) sacc[nt][3] = -1e30f;
            }
        }

        // ---- online softmax ----
        float m0 = -1e30f, m1 = -1e30f;
#pragma unroll
        for (int nt = 0; nt < 8; nt++) {
            m0 = fmaxf(m0, fmaxf(sacc[nt][0], sacc[nt][1]));
            m1 = fmaxf(m1, fmaxf(sacc[nt][2], sacc[nt][3]));
        }
        m0 = fmaxf(m0, __shfl_xor_sync(0xffffffffu, m0, 1));
        m0 = fmaxf(m0, __shfl_xor_sync(0xffffffffu, m0, 2));
        m1 = fmaxf(m1, __shfl_xor_sync(0xffffffffu, m1, 1));
        m1 = fmaxf(m1, __shfl_xor_sync(0xffffffffu, m1, 2));

        const float mn0 = fmaxf(mr0, m0);
        const float mn1 = fmaxf(mr1, m1);
        const float corr0 = __expf(mr0 - mn0);
        const float corr1 = __expf(mr1 - mn1);
        mr0 = mn0; mr1 = mn1;

        // p = exp(s - mn); pack into A-fragments for P*V (hi + lo)
        uint32_t aphi[4][4], aplo[4][4];
        float ps0 = 0.0f, ps1 = 0.0f;
#pragma unroll
        for (int kc2 = 0; kc2 < 4; kc2++) {
            const int ntE = 2 * kc2, ntO = 2 * kc2 + 1;
            float pE0 = __expf(sacc[ntE][0] - mn0);
            float pE1 = __expf(sacc[ntE][1] - mn0);
            float pE2 = __expf(sacc[ntE][2] - mn1);
            float pE3 = __expf(sacc[ntE][3] - mn1);
            float pO0 = __expf(sacc[ntO][0] - mn0);
            float pO1 = __expf(sacc[ntO][1] - mn0);
            float pO2 = __expf(sacc[ntO][2] - mn1);
            float pO3 = __expf(sacc[ntO][3] - mn1);
            ps0 += pE0 + pE1 + pO0 + pO1;
            ps1 += pE2 + pE3 + pO2 + pO3;
            split2(pE0, pE1, aphi[kc2][0], aplo[kc2][0]);
            split2(pE2, pE3, aphi[kc2][1], aplo[kc2][1]);
            split2(pO0, pO1, aphi[kc2][2], aplo[kc2][2]);
            split2(pO2, pO3, aphi[kc2][3], aplo[kc2][3]);
        }
        ps0 += __shfl_xor_sync(0xffffffffu, ps0, 1);
        ps0 += __shfl_xor_sync(0xffffffffu, ps0, 2);
        ps1 += __shfl_xor_sync(0xffffffffu, ps1, 1);
        ps1 += __shfl_xor_sync(0xffffffffu, ps1, 2);
        l0 = l0 * corr0 + ps0;
        l1 = l1 * corr1 + ps1;

        // rescale O accumulators
#pragma unroll
        for (int nt = 0; nt < 8; nt++) {
            oacc[nt][0] *= corr0; oacc[nt][1] *= corr0;
            oacc[nt][2] *= corr1; oacc[nt][3] *= corr1;
        }

        // ---- O += P V  (hi*hi + hi*lo + lo*hi) ----
#pragma unroll
        for (int kc2 = 0; kc2 < 4; kc2++) {
#pragma unroll
            for (int np = 0; np < 4; np++) {
                uint32_t bvh[4], bvl[4];
                ldsm4t(bV + kc2 * (16 * STRIDE) + np * 32, bvh);
                ldsm4t(bV + 9216 + kc2 * (16 * STRIDE) + np * 32, bvl);
                mma16816(oacc[2 * np],     aphi[kc2], bvh[0], bvh[1]);
                mma16816(oacc[2 * np],     aphi[kc2], bvl[0], bvl[1]);
                mma16816(oacc[2 * np],     aplo[kc2], bvh[0], bvh[1]);
                mma16816(oacc[2 * np + 1], aphi[kc2], bvh[2], bvh[3]);
                mma16816(oacc[2 * np + 1], aphi[kc2], bvl[2], bvl[3]);
                mma16816(oacc[2 * np + 1], aplo[kc2], bvh[2], bvh[3]);
            }
        }
    }

    // ---- epilogue ----
    const float inv0 = 1.0f / l0;
    const float inv1 = 1.0f / l1;
    const size_t row0 = (size_t)(b * SEQ) + q0 + R + g;
    const size_t row1 = row0 + 8;
#pragma unroll
    for (int nt = 0; nt < 8; nt++) {
        const int col = nt * 8 + qr * 2;
        float2 o0; o0.x = oacc[nt][0] * inv0; o0.y = oacc[nt][1] * inv0;
        float2 o1; o1.x = oacc[nt][2] * inv1; o1.y = oacc[nt][3] * inv1;
        *reinterpret_cast<float2*>(out + row0 * HEAD + col) = o0;
        *reinterpret_cast<float2*>(out + row1 * HEAD + col) = o1;
    }
}

// ===========================================================================
extern "C" void kernel_launch(void* const* d_in, const int* in_sizes, int n_in,
                              void* d_out, int out_size)
{
    const float* x  = (const float*)d_in[0];
    const float* Wq = (const float*)d_in[1];
    const float* bq = (const float*)d_in[2];
    const float* Wk = (const float*)d_in[3];
    const float* bk = (const float*)d_in[4];
    const float* Wv = (const float*)d_in[5];
    const float* bv = (const float*)d_in[6];
    float* out = (float*)d_out;

    {
        dim3 grid(BATCH * SEQ / 64);
        dim3 block(16, 16);
        qkv_kernel<<<grid, block>>>(x, Wq, bq, Wk, bk, Wv, bv);
    }

    {
        cudaFuncSetAttribute(attn_mma_kernel,
                             cudaFuncAttributeMaxDynamicSharedMemorySize, SM_TOTAL);
        attn_mma_kernel<<<256, 128, SM_TOTAL>>>(out);
    }
}

// round 4
// speedup vs baseline: 1.9132x; 1.5360x over previous
#include <cuda_runtime.h>
#include <cuda_bf16.h>
#include <math.h>
#include <cstdint>

#define BATCH 4
#define SEQ   4096
#define EMB   1024
#define HEAD  64
#define NPROJ 192

// bf16 hi/lo split of projected q (pre-scaled by 0.125), k, v. 2 MB each.
__device__ __nv_bfloat16 g_qhi[BATCH * SEQ * HEAD];
__device__ __nv_bfloat16 g_qlo[BATCH * SEQ * HEAD];
__device__ __nv_bfloat16 g_khi[BATCH * SEQ * HEAD];
__device__ __nv_bfloat16 g_klo[BATCH * SEQ * HEAD];
__device__ __nv_bfloat16 g_vhi[BATCH * SEQ * HEAD];
__device__ __nv_bfloat16 g_vlo[BATCH * SEQ * HEAD];

// ===========================================================================
// helpers
// ===========================================================================
__device__ __forceinline__ uint32_t smem_u32(const void* p) {
    uint32_t a;
    asm("{ .reg .u64 t; cvta.to.shared.u64 t, %1; cvt.u32.u64 %0, t; }"
        : "=r"(a) : "l"(p));
    return a;
}

__device__ __forceinline__ void ldsm4(uint32_t addr, uint32_t* r) {
    asm volatile("ldmatrix.sync.aligned.m8n8.x4.shared.b16 {%0,%1,%2,%3}, [%4];"
        : "=r"(r[0]), "=r"(r[1]), "=r"(r[2]), "=r"(r[3]) : "r"(addr));
}
__device__ __forceinline__ void ldsm4t(uint32_t addr, uint32_t* r) {
    asm volatile("ldmatrix.sync.aligned.m8n8.x4.trans.shared.b16 {%0,%1,%2,%3}, [%4];"
        : "=r"(r[0]), "=r"(r[1]), "=r"(r[2]), "=r"(r[3]) : "r"(addr));
}

// D += A * B   (m16n8k16, bf16 in, f32 accum)
__device__ __forceinline__ void mma16816(float* c, const uint32_t* a,
                                         uint32_t b0, uint32_t b1) {
    asm volatile(
        "mma.sync.aligned.m16n8k16.row.col.f32.bf16.bf16.f32 "
        "{%0,%1,%2,%3}, {%4,%5,%6,%7}, {%8,%9}, {%0,%1,%2,%3};"
        : "+f"(c[0]), "+f"(c[1]), "+f"(c[2]), "+f"(c[3])
        : "r"(a[0]), "r"(a[1]), "r"(a[2]), "r"(a[3]), "r"(b0), "r"(b1));
}

__device__ __forceinline__ void cp_async16(uint32_t saddr, const void* gaddr) {
    asm volatile("cp.async.cg.shared.global [%0], [%1], 16;"
        :: "r"(saddr), "l"(gaddr) : "memory");
}
#define CP_COMMIT() asm volatile("cp.async.commit_group;" ::: "memory")

__device__ __forceinline__ uint32_t pack2(__nv_bfloat16 lo, __nv_bfloat16 hi) {
    return (uint32_t)__bfloat16_as_ushort(lo) |
           ((uint32_t)__bfloat16_as_ushort(hi) << 16);
}

__device__ __forceinline__ void split2(float x0, float x1,
                                       uint32_t& hw, uint32_t& lw) {
    __nv_bfloat16 h0 = __float2bfloat16(x0);
    __nv_bfloat16 h1 = __float2bfloat16(x1);
    float l0 = x0 - __bfloat162float(h0);
    float l1 = x1 - __bfloat162float(h1);
    hw = pack2(h0, h1);
    lw = pack2(__float2bfloat16(l0), __float2bfloat16(l1));
}

// ===========================================================================
// Kernel 1: fused QKV projection (scalar mainloop; hi/lo bf16 epilogue)
// ===========================================================================
__global__ __launch_bounds__(256) void qkv_kernel(
    const float* __restrict__ x,
    const float* __restrict__ Wq, const float* __restrict__ bq,
    const float* __restrict__ Wk, const float* __restrict__ bk,
    const float* __restrict__ Wv, const float* __restrict__ bv)
{
    __shared__ float xs[64][33];
    __shared__ float ws[32][192];

    const int tx  = threadIdx.x;
    const int ty  = threadIdx.y;
    const int tid = ty * 16 + tx;
    const int row0 = blockIdx.x * 64;

    float acc[4][12];
#pragma unroll
    for (int i = 0; i < 4; i++)
#pragma unroll
        for (int j = 0; j < 12; j++) acc[i][j] = 0.0f;

    for (int k0 = 0; k0 < EMB; k0 += 32) {
        {
            const int m  = tid >> 2;
            const int ko = (tid & 3) * 8;
            const float4* src =
                reinterpret_cast<const float4*>(x + (size_t)(row0 + m) * EMB + k0 + ko);
            float4 v0 = src[0];
            float4 v1 = src[1];
            xs[m][ko + 0] = v0.x; xs[m][ko + 1] = v0.y;
            xs[m][ko + 2] = v0.z; xs[m][ko + 3] = v0.w;
            xs[m][ko + 4] = v1.x; xs[m][ko + 5] = v1.y;
            xs[m][ko + 6] = v1.z; xs[m][ko + 7] = v1.w;
        }
        for (int i = tid; i < 32 * NPROJ; i += 256) {
            const int k = i / NPROJ;
            const int c = i % NPROJ;
            float w;
            if (c < 64)       w = Wq[(k0 + k) * HEAD + c];
            else if (c < 128) w = Wk[(k0 + k) * HEAD + (c - 64)];
            else              w = Wv[(k0 + k) * HEAD + (c - 128)];
            ws[k][c] = w;
        }
        __syncthreads();

#pragma unroll
        for (int k = 0; k < 32; k++) {
            float a[4], b[12];
#pragma unroll
            for (int i = 0; i < 4; i++)  a[i] = xs[ty * 4 + i][k];
#pragma unroll
            for (int j = 0; j < 12; j++) b[j] = ws[k][tx * 12 + j];
#pragma unroll
            for (int i = 0; i < 4; i++)
#pragma unroll
                for (int j = 0; j < 12; j++)
                    acc[i][j] = fmaf(a[i], b[j], acc[i][j]);
        }
        __syncthreads();
    }

#pragma unroll
    for (int i = 0; i < 4; i++) {
        const size_t r = row0 + ty * 4 + i;
#pragma unroll
        for (int j = 0; j < 12; j += 2) {
            const int c = tx * 12 + j;
            float v0 = acc[i][j], v1 = acc[i][j + 1];
            __nv_bfloat16 *hiA, *loA;
            size_t idx;
            if (c < 64) {
                v0 = (v0 + bq[c]) * 0.125f;
                v1 = (v1 + bq[c + 1]) * 0.125f;
                hiA = g_qhi; loA = g_qlo; idx = r * HEAD + c;
            } else if (c < 128) {
                v0 += bk[c - 64]; v1 += bk[c - 63];
                hiA = g_khi; loA = g_klo; idx = r * HEAD + (c - 64);
            } else {
                v0 += bv[c - 128]; v1 += bv[c - 127];
                hiA = g_vhi; loA = g_vlo; idx = r * HEAD + (c - 128);
            }
            __nv_bfloat16 h0 = __float2bfloat16(v0);
            __nv_bfloat16 h1 = __float2bfloat16(v1);
            float l0 = v0 - __bfloat162float(h0);
            float l1 = v1 - __bfloat162float(h1);
            __nv_bfloat162 hh; hh.x = h0; hh.y = h1;
            __nv_bfloat162 ll; ll.x = __float2bfloat16(l0); ll.y = __float2bfloat16(l1);
            *reinterpret_cast<__nv_bfloat162*>(hiA + idx) = hh;
            *reinterpret_cast<__nv_bfloat162*>(loA + idx) = ll;
        }
    }
}

// ===========================================================================
// Kernel 2: flash attention on mma.sync bf16 (3xBF16), double-buffered cp.async
// BQ=64, BK=64, 128 threads. smem 92160 B -> 2 CTAs/SM.
// ===========================================================================
#define BQ 64
#define BK 64
#define STRIDE 144                 // smem row stride in bytes

#define SM_QHI   0
#define SM_QLO   9216
#define SM_STAGE 18432             // start of K/V stages
#define STAGE_SZ 36864             // khi,klo,vhi,vlo (4 * 9216)
#define OFF_KHI  0
#define OFF_KLO  9216
#define OFF_VHI  18432
#define OFF_VLO  27648
#define SM_TOTAL (SM_STAGE + 2 * STAGE_SZ)   // 92160

__global__ __launch_bounds__(128) void attn_mma_kernel(float* __restrict__ out)
{
    extern __shared__ char smem[];
    const uint32_t sbase = smem_u32(smem);

    const int u  = blockIdx.x;
    const int b  = u & 3;
    const int v_ = u >> 2;
    const int qt = (v_ & 1) ? (63 - (v_ >> 1)) : (v_ >> 1);  // long/short interleave
    const int q0 = qt * BQ;
    const int nk = qt + 1;

    const int tid  = threadIdx.x;
    const int warp = tid >> 5;
    const int lane = tid & 31;
    const int g    = lane >> 2;
    const int qr   = lane & 3;
    const int R    = warp * 16;

    // per-thread cp.async slots: 16 chunks of 16B (2048 total / 128 threads)
    // i = tid + t*128, arr = i>>9, rem = i&511, r = rem>>3, c = rem&7
    // Prefetch one K/V stage.
    auto prefetch = [&](int kt, int stage) {
        const uint32_t sb = sbase + SM_STAGE + stage * STAGE_SZ;
        const size_t gro = (size_t)(b * SEQ) + (size_t)kt * BK;
#pragma unroll
        for (int t = 0; t < 16; t++) {
            const int i   = tid + t * 128;
            const int arr = i >> 9;
            const int rem = i & 511;
            const int r = rem >> 3, c = rem & 7;
            const __nv_bfloat16* base;
            uint32_t off;
            if (arr == 0)      { base = g_khi; off = OFF_KHI; }
            else if (arr == 1) { base = g_klo; off = OFF_KLO; }
            else if (arr == 2) { base = g_vhi; off = OFF_VHI; }
            else               { base = g_vlo; off = OFF_VLO; }
            cp_async16(sb + off + r * STRIDE + c * 16,
                       base + (gro + r) * HEAD + c * 8);
        }
        CP_COMMIT();
    };

    // ---- prefetch K/V tile 0 ----
    prefetch(0, 0);

    // ---- load Q tile (hi+lo) into smem ----
    for (int i = tid; i < 1024; i += 128) {
        const int arr = i >> 9;
        const int rem = i & 511;
        const int r = rem >> 3, c = rem & 7;
        const __nv_bfloat16* src = (arr == 0 ? g_qhi : g_qlo)
            + ((size_t)(b * SEQ) + q0 + r) * HEAD + c * 8;
        const int4 val = *reinterpret_cast<const int4*>(src);
        *reinterpret_cast<int4*>(smem + (arr == 0 ? SM_QHI : SM_QLO)
                                 + r * STRIDE + c * 16) = val;
    }
    __syncthreads();

    // ---- cache Q A-fragments ----
    const uint32_t aQ = sbase + SM_QHI
        + (uint32_t)(R + (lane & 15)) * STRIDE + ((lane >> 4) * 8) * 2;
    uint32_t qahi[4][4], qalo[4][4];
#pragma unroll
    for (int kc = 0; kc < 4; kc++) {
        ldsm4(aQ + kc * 32, qahi[kc]);
        ldsm4(aQ + 9216 + kc * 32, qalo[kc]);
    }

    // lane-relative ldmatrix offsets (within a stage)
    const uint32_t oK = (uint32_t)(((lane >> 4) & 1) * 8 + (lane & 7)) * STRIDE
        + (((lane >> 3) & 1) * 8) * 2;
    const uint32_t oV = (uint32_t)(((lane >> 3) & 1) * 8 + (lane & 7)) * STRIDE
        + (((lane >> 4) & 1) * 8) * 2;

    float oacc[8][4];
#pragma unroll
    for (int nt = 0; nt < 8; nt++)
#pragma unroll
        for (int e = 0; e < 4; e++) oacc[nt][e] = 0.0f;
    float mr0 = -1e30f, mr1 = -1e30f, l0 = 0.0f, l1 = 0.0f;

    for (int kt = 0; kt < nk; kt++) {
        __syncthreads();   // all warps done computing on the buffer we prefetch into
        if (kt + 1 < nk) {
            prefetch(kt + 1, (kt + 1) & 1);
            asm volatile("cp.async.wait_group 1;" ::: "memory");
        } else {
            asm volatile("cp.async.wait_group 0;" ::: "memory");
        }
        __syncthreads();

        const uint32_t sb = sbase + SM_STAGE + (kt & 1) * STAGE_SZ;
        const uint32_t bK = sb + OFF_KHI + oK;
        const uint32_t bV = sb + OFF_VHI + oV;

        // ---- S = Q K^T  (hi*hi + hi*lo + lo*hi) ----
        float sacc[8][4];
#pragma unroll
        for (int nt = 0; nt < 8; nt++)
#pragma unroll
            for (int e = 0; e < 4; e++) sacc[nt][e] = 0.0f;

#pragma unroll
        for (int kc = 0; kc < 4; kc++) {
#pragma unroll
            for (int np = 0; np < 4; np++) {
                uint32_t bh[4], bl[4];
                ldsm4(bK + np * (16 * STRIDE) + kc * 32, bh);
                ldsm4(bK + 9216 + np * (16 * STRIDE) + kc * 32, bl);
                mma16816(sacc[2 * np],     qahi[kc], bh[0], bh[1]);
                mma16816(sacc[2 * np],     qahi[kc], bl[0], bl[1]);
                mma16816(sacc[2 * np],     qalo[kc], bh[0], bh[1]);
                mma16816(sacc[2 * np + 1], qahi[kc], bh[2], bh[3]);
                mma16816(sacc[2 * np + 1], qahi[kc], bl[2], bl[3]);
                mma16816(sacc[2 * np + 1], qalo[kc], bh[2], bh[3]);
            }
        }

        // ---- causal mask (diagonal tile only) ----
        if (kt == qt) {
            const int lr0 = R + g, lr1 = R + g + 8;
#pragma unroll
            for (int nt = 0; nt < 8; nt++) {
                const int lc = nt * 8 + qr * 2;
                if (lc > lr0)     sacc[nt][0] = -1e30f;
                if (lc + 1 > lr0) sacc[nt][1] = -1e30f;
                if (lc > lr1)     sacc[nt][2] = -1e30f;
                if (lc + 1 > lr1) sacc[nt][3] = -1e30f;
            }
        }

        // ---- online softmax ----
        float m0 = -1e30f, m1 = -1e30f;
#pragma unroll
        for (int nt = 0; nt < 8; nt++) {
            m0 = fmaxf(m0, fmaxf(sacc[nt][0], sacc[nt][1]));
            m1 = fmaxf(m1, fmaxf(sacc[nt][2], sacc[nt][3]));
        }
        m0 = fmaxf(m0, __shfl_xor_sync(0xffffffffu, m0, 1));
        m0 = fmaxf(m0, __shfl_xor_sync(0xffffffffu, m0, 2));
        m1 = fmaxf(m1, __shfl_xor_sync(0xffffffffu, m1, 1));
        m1 = fmaxf(m1, __shfl_xor_sync(0xffffffffu, m1, 2));

        const float mn0 = fmaxf(mr0, m0);
        const float mn1 = fmaxf(mr1, m1);
        const float corr0 = __expf(mr0 - mn0);
        const float corr1 = __expf(mr1 - mn1);
        mr0 = mn0; mr1 = mn1;

        uint32_t aphi[4][4], aplo[4][4];
        float ps0 = 0.0f, ps1 = 0.0f;
#pragma unroll
        for (int kc2 = 0; kc2 < 4; kc2++) {
            const int ntE = 2 * kc2, ntO = 2 * kc2 + 1;
            float pE0 = __expf(sacc[ntE][0] - mn0);
            float pE1 = __expf(sacc[ntE][1] - mn0);
            float pE2 = __expf(sacc[ntE][2] - mn1);
            float pE3 = __expf(sacc[ntE][3] - mn1);
            float pO0 = __expf(sacc[ntO][0] - mn0);
            float pO1 = __expf(sacc[ntO][1] - mn0);
            float pO2 = __expf(sacc[ntO][2] - mn1);
            float pO3 = __expf(sacc[ntO][3] - mn1);
            ps0 += pE0 + pE1 + pO0 + pO1;
            ps1 += pE2 + pE3 + pO2 + pO3;
            split2(pE0, pE1, aphi[kc2][0], aplo[kc2][0]);
            split2(pE2, pE3, aphi[kc2][1], aplo[kc2][1]);
            split2(pO0, pO1, aphi[kc2][2], aplo[kc2][2]);
            split2(pO2, pO3, aphi[kc2][3], aplo[kc2][3]);
        }
        ps0 += __shfl_xor_sync(0xffffffffu, ps0, 1);
        ps0 += __shfl_xor_sync(0xffffffffu, ps0, 2);
        ps1 += __shfl_xor_sync(0xffffffffu, ps1, 1);
        ps1 += __shfl_xor_sync(0xffffffffu, ps1, 2);
        l0 = l0 * corr0 + ps0;
        l1 = l1 * corr1 + ps1;

#pragma unroll
        for (int nt = 0; nt < 8; nt++) {
            oacc[nt][0] *= corr0; oacc[nt][1] *= corr0;
            oacc[nt][2] *= corr1; oacc[nt][3] *= corr1;
        }

        // ---- O += P V  (hi*hi + hi*lo + lo*hi) ----
#pragma unroll
        for (int kc2 = 0; kc2 < 4; kc2++) {
#pragma unroll
            for (int np = 0; np < 4; np++) {
                uint32_t bvh[4], bvl[4];
                ldsm4t(bV + kc2 * (16 * STRIDE) + np * 32, bvh);
                ldsm4t(bV + 9216 + kc2 * (16 * STRIDE) + np * 32, bvl);
                mma16816(oacc[2 * np],     aphi[kc2], bvh[0], bvh[1]);
                mma16816(oacc[2 * np],     aphi[kc2], bvl[0], bvl[1]);
                mma16816(oacc[2 * np],     aplo[kc2], bvh[0], bvh[1]);
                mma16816(oacc[2 * np + 1], aphi[kc2], bvh[2], bvh[3]);
                mma16816(oacc[2 * np + 1], aphi[kc2], bvl[2], bvl[3]);
                mma16816(oacc[2 * np + 1], aplo[kc2], bvh[2], bvh[3]);
            }
        }
    }

    // ---- epilogue ----
    const float inv0 = 1.0f / l0;
    const float inv1 = 1.0f / l1;
    const size_t row0 = (size_t)(b * SEQ) + q0 + R + g;
    const size_t row1 = row0 + 8;
#pragma unroll
    for (int nt = 0; nt < 8; nt++) {
        const int col = nt * 8 + qr * 2;
        float2 o0; o0.x = oacc[nt][0] * inv0; o0.y = oacc[nt][1] * inv0;
        float2 o1; o1.x = oacc[nt][2] * inv1; o1.y = oacc[nt][3] * inv1;
        *reinterpret_cast<float2*>(out + row0 * HEAD + col) = o0;
        *reinterpret_cast<float2*>(out + row1 * HEAD + col) = o1;
    }
}

// ===========================================================================
extern "C" void kernel_launch(void* const* d_in, const int* in_sizes, int n_in,
                              void* d_out, int out_size)
{
    const float* x  = (const float*)d_in[0];
    const float* Wq = (const float*)d_in[1];
    const float* bq = (const float*)d_in[2];
    const float* Wk = (const float*)d_in[3];
    const float* bk = (const float*)d_in[4];
    const float* Wv = (const float*)d_in[5];
    const float* bv = (const float*)d_in[6];
    float* out = (float*)d_out;

    {
        dim3 grid(BATCH * SEQ / 64);
        dim3 block(16, 16);
        qkv_kernel<<<grid, block>>>(x, Wq, bq, Wk, bk, Wv, bv);
    }

    {
        cudaFuncSetAttribute(attn_mma_kernel,
                             cudaFuncAttributeMaxDynamicSharedMemorySize, SM_TOTAL);
        attn_mma_kernel<<<256, 128, SM_TOTAL>>>(out);
    }
}

// round 6
// speedup vs baseline: 3.5882x; 1.8755x over previous
#include <cuda_runtime.h>
#include <cuda_bf16.h>
#include <math.h>
#include <cstdint>

#define BATCH 4
#define SEQ   4096
#define EMB   1024
#define HEAD  64

// bf16 hi/lo split of projected q (pre-scaled by 0.125), k, v. 2 MB each.
__device__ __nv_bfloat16 g_qhi[BATCH * SEQ * HEAD];
__device__ __nv_bfloat16 g_qlo[BATCH * SEQ * HEAD];
__device__ __nv_bfloat16 g_khi[BATCH * SEQ * HEAD];
__device__ __nv_bfloat16 g_klo[BATCH * SEQ * HEAD];
__device__ __nv_bfloat16 g_vhi[BATCH * SEQ * HEAD];
__device__ __nv_bfloat16 g_vlo[BATCH * SEQ * HEAD];

// W^T hi/lo: [n=192][k=1024], n<64 = Wq, <128 = Wk, else Wv
__device__ __nv_bfloat16 g_wthi[192 * 1024];
__device__ __nv_bfloat16 g_wtlo[192 * 1024];

// ===========================================================================
// helpers
// ===========================================================================
__device__ __forceinline__ uint32_t smem_u32(const void* p) {
    uint32_t a;
    asm("{ .reg .u64 t; cvta.to.shared.u64 t, %1; cvt.u32.u64 %0, t; }"
        : "=r"(a) : "l"(p));
    return a;
}

__device__ __forceinline__ void ldsm4(uint32_t addr, uint32_t* r) {
    asm volatile("ldmatrix.sync.aligned.m8n8.x4.shared.b16 {%0,%1,%2,%3}, [%4];"
        : "=r"(r[0]), "=r"(r[1]), "=r"(r[2]), "=r"(r[3]) : "r"(addr));
}
__device__ __forceinline__ void ldsm4t(uint32_t addr, uint32_t* r) {
    asm volatile("ldmatrix.sync.aligned.m8n8.x4.trans.shared.b16 {%0,%1,%2,%3}, [%4];"
        : "=r"(r[0]), "=r"(r[1]), "=r"(r[2]), "=r"(r[3]) : "r"(addr));
}

__device__ __forceinline__ void mma16816(float* c, const uint32_t* a,
                                         uint32_t b0, uint32_t b1) {
    asm volatile(
        "mma.sync.aligned.m16n8k16.row.col.f32.bf16.bf16.f32 "
        "{%0,%1,%2,%3}, {%4,%5,%6,%7}, {%8,%9}, {%0,%1,%2,%3};"
        : "+f"(c[0]), "+f"(c[1]), "+f"(c[2]), "+f"(c[3])
        : "r"(a[0]), "r"(a[1]), "r"(a[2]), "r"(a[3]), "r"(b0), "r"(b1));
}

__device__ __forceinline__ void cp_async16(uint32_t saddr, const void* gaddr) {
    asm volatile("cp.async.cg.shared.global [%0], [%1], 16;"
        :: "r"(saddr), "l"(gaddr) : "memory");
}
#define CP_COMMIT() asm volatile("cp.async.commit_group;" ::: "memory")

#define STS128(r0, r1, r2, r3, addr) \
    asm volatile("st.shared.v4.b32 [%0], {%1, %2, %3, %4};" \
        :: "r"(addr), "r"(r0), "r"(r1), "r"(r2), "r"(r3) : "memory")

__device__ __forceinline__ uint32_t pack2(__nv_bfloat16 lo, __nv_bfloat16 hi) {
    return (uint32_t)__bfloat16_as_ushort(lo) |
           ((uint32_t)__bfloat16_as_ushort(hi) << 16);
}

__device__ __forceinline__ void split2(float x0, float x1,
                                       uint32_t& hw, uint32_t& lw) {
    __nv_bfloat16 h0 = __float2bfloat16(x0);
    __nv_bfloat16 h1 = __float2bfloat16(x1);
    float l0 = x0 - __bfloat162float(h0);
    float l1 = x1 - __bfloat162float(h1);
    hw = pack2(h0, h1);
    lw = pack2(__float2bfloat16(l0), __float2bfloat16(l1));
}

// ===========================================================================
// Kernel 0: W^T hi/lo precompute
// ===========================================================================
__global__ __launch_bounds__(256) void wconv_kernel(
    const float* __restrict__ Wq, const float* __restrict__ Wk,
    const float* __restrict__ Wv)
{
    const int n = blockIdx.x;
    const float* W;
    int nn;
    if (n < 64)       { W = Wq; nn = n; }
    else if (n < 128) { W = Wk; nn = n - 64; }
    else              { W = Wv; nn = n - 128; }
    for (int k = threadIdx.x; k < 1024; k += 256) {
        float v = W[(size_t)k * HEAD + nn];
        __nv_bfloat16 h = __float2bfloat16(v);
        float l = v - __bfloat162float(h);
        g_wthi[(size_t)n * 1024 + k] = h;
        g_wtlo[(size_t)n * 1024 + k] = __float2bfloat16(l);
    }
}

// ===========================================================================
// Kernel 1: QKV projection on mma.sync (3xBF16).
// C[16384,192] = x[16384,1024] @ W^T. CTA: 128 rows x 192 cols. 256 thr.
// K-chunk 64 -> NCH = EMB/64 = 16 chunks (R5 bug: looped 64 -> OOB on x).
// ===========================================================================
#define QK_STG  92160
#define QX_HI   0
#define QX_LO   18432
#define QW_HI   36864
#define QW_LO   64512
#define QK_SMEM (2 * QK_STG)   // 184320
#define NCH     (EMB / 64)     // 16

__global__ __launch_bounds__(256) void qkv_mma_kernel(
    const float* __restrict__ x,
    const float* __restrict__ bq, const float* __restrict__ bk,
    const float* __restrict__ bv)
{
    extern __shared__ char smem[];
    const uint32_t sbase = smem_u32(smem);
    const int tid  = threadIdx.x;
    const int warp = tid >> 5;
    const int lane = tid & 31;
    const int g    = lane >> 2;
    const int qr   = lane & 3;
    const int warpM = warp >> 1;
    const int warpN = warp & 1;
    const int m0 = blockIdx.x * 128;

    float xr[32];

    // load x chunk c into registers (row = tid>>1, half = tid&1, 32 fp32)
    auto ldX = [&](int c) {
        const float4* src = reinterpret_cast<const float4*>(
            x + (size_t)(m0 + (tid >> 1)) * EMB + c * 64 + (tid & 1) * 32);
#pragma unroll
        for (int j = 0; j < 8; j++) {
            float4 v = src[j];
            xr[j * 4 + 0] = v.x; xr[j * 4 + 1] = v.y;
            xr[j * 4 + 2] = v.z; xr[j * 4 + 3] = v.w;
        }
    };

    // split regs -> bf16 hi/lo smem stage s
    auto stX = [&](int s) {
        const uint32_t dst = sbase + s * QK_STG
            + (uint32_t)(tid >> 1) * 144 + (tid & 1) * 64;
#pragma unroll
        for (int j = 0; j < 4; j++) {
            uint32_t hw[4], lw[4];
#pragma unroll
            for (int p = 0; p < 4; p++)
                split2(xr[j * 8 + p * 2], xr[j * 8 + p * 2 + 1], hw[p], lw[p]);
            STS128(hw[0], hw[1], hw[2], hw[3], dst + QX_HI + j * 16);
            STS128(lw[0], lw[1], lw[2], lw[3], dst + QX_LO + j * 16);
        }
    };

    // cp.async W^T chunk c (hi+lo, 192 rows x 64 k) into stage s
    auto cpW = [&](int c, int s) {
        const uint32_t base = sbase + s * QK_STG;
#pragma unroll
        for (int t = 0; t < 12; t++) {
            const int i   = tid + t * 256;
            const int arr = (i >= 1536) ? 1 : 0;
            const int i2  = arr ? (i - 1536) : i;
            const int row = i2 >> 3, ch = i2 & 7;
            const __nv_bfloat16* src = (arr ? g_wtlo : g_wthi)
                + (size_t)row * 1024 + c * 64 + ch * 8;
            cp_async16(base + (arr ? QW_LO : QW_HI) + row * 144 + ch * 16, src);
        }
        CP_COMMIT();
    };

    float acc[2][12][4];
#pragma unroll
    for (int mt = 0; mt < 2; mt++)
#pragma unroll
        for (int nt = 0; nt < 12; nt++)
#pragma unroll
            for (int e = 0; e < 4; e++) acc[mt][nt][e] = 0.0f;

    ldX(0);
    cpW(0, 0);

    for (int c = 0; c < NCH; c++) {
        const int s = c & 1;
        __syncthreads();                 // all warps done with stage s mma
        stX(s);
        if (c + 1 < NCH) {
            cpW(c + 1, s ^ 1);
            asm volatile("cp.async.wait_group 1;" ::: "memory");
        } else {
            asm volatile("cp.async.wait_group 0;" ::: "memory");
        }
        __syncthreads();
        if (c + 1 < NCH) ldX(c + 1);     // LDG in flight during mma below

        const uint32_t xb = sbase + s * QK_STG + QX_HI
            + (uint32_t)(warpM * 32 + (lane & 15)) * 144 + (lane >> 4) * 16;
        const uint32_t wb = sbase + s * QK_STG + QW_HI
            + (uint32_t)(warpN * 96 + ((lane >> 4) & 1) * 8 + (lane & 7)) * 144
            + ((lane >> 3) & 1) * 16;

#pragma unroll
        for (int kc = 0; kc < 4; kc++) {
            uint32_t ah0[4], ah1[4], al0[4], al1[4];
            ldsm4(xb + kc * 32, ah0);
            ldsm4(xb + 16 * 144 + kc * 32, ah1);
            ldsm4(xb + (QX_LO - QX_HI) + kc * 32, al0);
            ldsm4(xb + (QX_LO - QX_HI) + 16 * 144 + kc * 32, al1);
#pragma unroll
            for (int nt = 0; nt < 6; nt++) {
                uint32_t bh[4], bl[4];
                ldsm4(wb + nt * (16 * 144) + kc * 32, bh);
                ldsm4(wb + (QW_LO - QW_HI) + nt * (16 * 144) + kc * 32, bl);
                mma16816(acc[0][2 * nt],     ah0, bh[0], bh[1]);
                mma16816(acc[0][2 * nt],     ah0, bl[0], bl[1]);
                mma16816(acc[0][2 * nt],     al0, bh[0], bh[1]);
                mma16816(acc[0][2 * nt + 1], ah0, bh[2], bh[3]);
                mma16816(acc[0][2 * nt + 1], ah0, bl[2], bl[3]);
                mma16816(acc[0][2 * nt + 1], al0, bh[2], bh[3]);
                mma16816(acc[1][2 * nt],     ah1, bh[0], bh[1]);
                mma16816(acc[1][2 * nt],     ah1, bl[0], bl[1]);
                mma16816(acc[1][2 * nt],     al1, bh[0], bh[1]);
                mma16816(acc[1][2 * nt + 1], ah1, bh[2], bh[3]);
                mma16816(acc[1][2 * nt + 1], ah1, bl[2], bl[3]);
                mma16816(acc[1][2 * nt + 1], al1, bh[2], bh[3]);
            }
        }
    }

    // ---- epilogue: bias (+0.125 scale for q), hi/lo split, write ----
#pragma unroll
    for (int mt = 0; mt < 2; mt++) {
        const int rbase = m0 + warpM * 32 + mt * 16 + g;
#pragma unroll
        for (int nt = 0; nt < 12; nt++) {
            const int cc = warpN * 96 + nt * 8 + qr * 2;
#pragma unroll
            for (int half = 0; half < 2; half++) {
                const int r = rbase + half * 8;
                float a0 = acc[mt][nt][half * 2 + 0];
                float a1 = acc[mt][nt][half * 2 + 1];
                __nv_bfloat16 *hiA, *loA;
                int col;
                if (cc < 64) {
                    col = cc;
                    a0 = (a0 + bq[col]) * 0.125f;
                    a1 = (a1 + bq[col + 1]) * 0.125f;
                    hiA = g_qhi; loA = g_qlo;
                } else if (cc < 128) {
                    col = cc - 64;
                    a0 += bk[col]; a1 += bk[col + 1];
                    hiA = g_khi; loA = g_klo;
                } else {
                    col = cc - 128;
                    a0 += bv[col]; a1 += bv[col + 1];
                    hiA = g_vhi; loA = g_vlo;
                }
                uint32_t hw, lw;
                split2(a0, a1, hw, lw);
                const size_t idx = (size_t)r * HEAD + col;
                *reinterpret_cast<uint32_t*>(hiA + idx) = hw;
                *reinterpret_cast<uint32_t*>(loA + idx) = lw;
            }
        }
    }
}

// ===========================================================================
// Kernel 2: flash attention on mma.sync bf16 (3xBF16), double-buffered cp.async
// (unchanged from R4: 181us)
// ===========================================================================
#define BQ 64
#define BK 64
#define STRIDE 144

#define SM_QHI   0
#define SM_QLO   9216
#define SM_STAGE 18432
#define STAGE_SZ 36864
#define OFF_KHI  0
#define OFF_KLO  9216
#define OFF_VHI  18432
#define OFF_VLO  27648
#define SM_TOTAL (SM_STAGE + 2 * STAGE_SZ)   // 92160

__global__ __launch_bounds__(128) void attn_mma_kernel(float* __restrict__ out)
{
    extern __shared__ char smem[];
    const uint32_t sbase = smem_u32(smem);

    const int u  = blockIdx.x;
    const int b  = u & 3;
    const int v_ = u >> 2;
    const int qt = (v_ & 1) ? (63 - (v_ >> 1)) : (v_ >> 1);
    const int q0 = qt * BQ;
    const int nk = qt + 1;

    const int tid  = threadIdx.x;
    const int warp = tid >> 5;
    const int lane = tid & 31;
    const int g    = lane >> 2;
    const int qr   = lane & 3;
    const int R    = warp * 16;

    auto prefetch = [&](int kt, int stage) {
        const uint32_t sb = sbase + SM_STAGE + stage * STAGE_SZ;
        const size_t gro = (size_t)(b * SEQ) + (size_t)kt * BK;
#pragma unroll
        for (int t = 0; t < 16; t++) {
            const int i   = tid + t * 128;
            const int arr = i >> 9;
            const int rem = i & 511;
            const int r = rem >> 3, c = rem & 7;
            const __nv_bfloat16* base;
            uint32_t off;
            if (arr == 0)      { base = g_khi; off = OFF_KHI; }
            else if (arr == 1) { base = g_klo; off = OFF_KLO; }
            else if (arr == 2) { base = g_vhi; off = OFF_VHI; }
            else               { base = g_vlo; off = OFF_VLO; }
            cp_async16(sb + off + r * STRIDE + c * 16,
                       base + (gro + r) * HEAD + c * 8);
        }
        CP_COMMIT();
    };

    prefetch(0, 0);

    for (int i = tid; i < 1024; i += 128) {
        const int arr = i >> 9;
        const int rem = i & 511;
        const int r = rem >> 3, c = rem & 7;
        const __nv_bfloat16* src = (arr == 0 ? g_qhi : g_qlo)
            + ((size_t)(b * SEQ) + q0 + r) * HEAD + c * 8;
        const int4 val = *reinterpret_cast<const int4*>(src);
        *reinterpret_cast<int4*>(smem + (arr == 0 ? SM_QHI : SM_QLO)
                                 + r * STRIDE + c * 16) = val;
    }
    __syncthreads();

    const uint32_t aQ = sbase + SM_QHI
        + (uint32_t)(R + (lane & 15)) * STRIDE + ((lane >> 4) * 8) * 2;
    uint32_t qahi[4][4], qalo[4][4];
#pragma unroll
    for (int kc = 0; kc < 4; kc++) {
        ldsm4(aQ + kc * 32, qahi[kc]);
        ldsm4(aQ + 9216 + kc * 32, qalo[kc]);
    }

    const uint32_t oK = (uint32_t)(((lane >> 4) & 1) * 8 + (lane & 7)) * STRIDE
        + (((lane >> 3) & 1) * 8) * 2;
    const uint32_t oV = (uint32_t)(((lane >> 3) & 1) * 8 + (lane & 7)) * STRIDE
        + (((lane >> 4) & 1) * 8) * 2;

    float oacc[8][4];
#pragma unroll
    for (int nt = 0; nt < 8; nt++)
#pragma unroll
        for (int e = 0; e < 4; e++) oacc[nt][e] = 0.0f;
    float mr0 = -1e30f, mr1 = -1e30f, l0 = 0.0f, l1 = 0.0f;

    for (int kt = 0; kt < nk; kt++) {
        __syncthreads();
        if (kt + 1 < nk) {
            prefetch(kt + 1, (kt + 1) & 1);
            asm volatile("cp.async.wait_group 1;" ::: "memory");
        } else {
            asm volatile("cp.async.wait_group 0;" ::: "memory");
        }
        __syncthreads();

        const uint32_t sb = sbase + SM_STAGE + (kt & 1) * STAGE_SZ;
        const uint32_t bK = sb + OFF_KHI + oK;
        const uint32_t bV = sb + OFF_VHI + oV;

        float sacc[8][4];
#pragma unroll
        for (int nt = 0; nt < 8; nt++)
#pragma unroll
            for (int e = 0; e < 4; e++) sacc[nt][e] = 0.0f;

#pragma unroll
        for (int kc = 0; kc < 4; kc++) {
#pragma unroll
            for (int np = 0; np < 4; np++) {
                uint32_t bh[4], bl[4];
                ldsm4(bK + np * (16 * STRIDE) + kc * 32, bh);
                ldsm4(bK + 9216 + np * (16 * STRIDE) + kc * 32, bl);
                mma16816(sacc[2 * np],     qahi[kc], bh[0], bh[1]);
                mma16816(sacc[2 * np],     qahi[kc], bl[0], bl[1]);
                mma16816(sacc[2 * np],     qalo[kc], bh[0], bh[1]);
                mma16816(sacc[2 * np + 1], qahi[kc], bh[2], bh[3]);
                mma16816(sacc[2 * np + 1], qahi[kc], bl[2], bl[3]);
                mma16816(sacc[2 * np + 1], qalo[kc], bh[2], bh[3]);
            }
        }

        if (kt == qt) {
            const int lr0 = R + g, lr1 = R + g + 8;
#pragma unroll
            for (int nt = 0; nt < 8; nt++) {
                const int lc = nt * 8 + qr * 2;
                if (lc > lr0)     sacc[nt][0] = -1e30f;
                if (lc + 1 > lr0) sacc[nt][1] = -1e30f;
                if (lc > lr1)     sacc[nt][2] = -1e30f;
                if (lc + 1 > lr1) sacc[nt][3] = -1e30f;
            }
        }

        float m0 = -1e30f, m1 = -1e30f;
#pragma unroll
        for (int nt = 0; nt < 8; nt++) {
            m0 = fmaxf(m0, fmaxf(sacc[nt][0], sacc[nt][1]));
            m1 = fmaxf(m1, fmaxf(sacc[nt][2], sacc[nt][3]));
        }
        m0 = fmaxf(m0, __shfl_xor_sync(0xffffffffu, m0, 1));
        m0 = fmaxf(m0, __shfl_xor_sync(0xffffffffu, m0, 2));
        m1 = fmaxf(m1, __shfl_xor_sync(0xffffffffu, m1, 1));
        m1 = fmaxf(m1, __shfl_xor_sync(0xffffffffu, m1, 2));

        const float mn0 = fmaxf(mr0, m0);
        const float mn1 = fmaxf(mr1, m1);
        const float corr0 = __expf(mr0 - mn0);
        const float corr1 = __expf(mr1 - mn1);
        mr0 = mn0; mr1 = mn1;

        uint32_t aphi[4][4], aplo[4][4];
        float ps0 = 0.0f, ps1 = 0.0f;
#pragma unroll
        for (int kc2 = 0; kc2 < 4; kc2++) {
            const int ntE = 2 * kc2, ntO = 2 * kc2 + 1;
            float pE0 = __expf(sacc[ntE][0] - mn0);
            float pE1 = __expf(sacc[ntE][1] - mn0);
            float pE2 = __expf(sacc[ntE][2] - mn1);
            float pE3 = __expf(sacc[ntE][3] - mn1);
            float pO0 = __expf(sacc[ntO][0] - mn0);
            float pO1 = __expf(sacc[ntO][1] - mn0);
            float pO2 = __expf(sacc[ntO][2] - mn1);
            float pO3 = __expf(sacc[ntO][3] - mn1);
            ps0 += pE0 + pE1 + pO0 + pO1;
            ps1 += pE2 + pE3 + pO2 + pO3;
            split2(pE0, pE1, aphi[kc2][0], aplo[kc2][0]);
            split2(pE2, pE3, aphi[kc2][1], aplo[kc2][1]);
            split2(pO0, pO1, aphi[kc2][2], aplo[kc2][2]);
            split2(pO2, pO3, aphi[kc2][3], aplo[kc2][3]);
        }
        ps0 += __shfl_xor_sync(0xffffffffu, ps0, 1);
        ps0 += __shfl_xor_sync(0xffffffffu, ps0, 2);
        ps1 += __shfl_xor_sync(0xffffffffu, ps1, 1);
        ps1 += __shfl_xor_sync(0xffffffffu, ps1, 2);
        l0 = l0 * corr0 + ps0;
        l1 = l1 * corr1 + ps1;

#pragma unroll
        for (int nt = 0; nt < 8; nt++) {
            oacc[nt][0] *= corr0; oacc[nt][1] *= corr0;
            oacc[nt][2] *= corr1; oacc[nt][3] *= corr1;
        }

#pragma unroll
        for (int kc2 = 0; kc2 < 4; kc2++) {
#pragma unroll
            for (int np = 0; np < 4; np++) {
                uint32_t bvh[4], bvl[4];
                ldsm4t(bV + kc2 * (16 * STRIDE) + np * 32, bvh);
                ldsm4t(bV + 9216 + kc2 * (16 * STRIDE) + np * 32, bvl);
                mma16816(oacc[2 * np],     aphi[kc2], bvh[0], bvh[1]);
                mma16816(oacc[2 * np],     aphi[kc2], bvl[0], bvl[1]);
                mma16816(oacc[2 * np],     aplo[kc2], bvh[0], bvh[1]);
                mma16816(oacc[2 * np + 1], aphi[kc2], bvh[2], bvh[3]);
                mma16816(oacc[2 * np + 1], aphi[kc2], bvl[2], bvl[3]);
                mma16816(oacc[2 * np + 1], aplo[kc2], bvh[2], bvh[3]);
            }
        }
    }

    const float inv0 = 1.0f / l0;
    const float inv1 = 1.0f / l1;
    const size_t row0 = (size_t)(b * SEQ) + q0 + R + g;
    const size_t row1 = row0 + 8;
#pragma unroll
    for (int nt = 0; nt < 8; nt++) {
        const int col = nt * 8 + qr * 2;
        float2 o0; o0.x = oacc[nt][0] * inv0; o0.y = oacc[nt][1] * inv0;
        float2 o1; o1.x = oacc[nt][2] * inv1; o1.y = oacc[nt][3] * inv1;
        *reinterpret_cast<float2*>(out + row0 * HEAD + col) = o0;
        *reinterpret_cast<float2*>(out + row1 * HEAD + col) = o1;
    }
}

// ===========================================================================
extern "C" void kernel_launch(void* const* d_in, const int* in_sizes, int n_in,
                              void* d_out, int out_size)
{
    const float* x  = (const float*)d_in[0];
    const float* Wq = (const float*)d_in[1];
    const float* bq = (const float*)d_in[2];
    const float* Wk = (const float*)d_in[3];
    const float* bk = (const float*)d_in[4];
    const float* Wv = (const float*)d_in[5];
    const float* bv = (const float*)d_in[6];
    float* out = (float*)d_out;

    wconv_kernel<<<192, 256>>>(Wq, Wk, Wv);

    {
        cudaFuncSetAttribute(qkv_mma_kernel,
                             cudaFuncAttributeMaxDynamicSharedMemorySize, QK_SMEM);
        qkv_mma_kernel<<<128, 256, QK_SMEM>>>(x, bq, bk, bv);
    }

    {
        cudaFuncSetAttribute(attn_mma_kernel,
                             cudaFuncAttributeMaxDynamicSharedMemorySize, SM_TOTAL);
        attn_mma_kernel<<<256, 128, SM_TOTAL>>>(out);
    }
}

// round 7
// speedup vs baseline: 3.6187x; 1.0085x over previous
#include <cuda_runtime.h>
#include <cuda_bf16.h>
#include <math.h>
#include <cstdint>

#define BATCH 4
#define SEQ   4096
#define EMB   1024
#define HEAD  64

// bf16 hi/lo split of projected q (pre-scaled by 0.125), k, v. 2 MB each.
__device__ __nv_bfloat16 g_qhi[BATCH * SEQ * HEAD];
__device__ __nv_bfloat16 g_qlo[BATCH * SEQ * HEAD];
__device__ __nv_bfloat16 g_khi[BATCH * SEQ * HEAD];
__device__ __nv_bfloat16 g_klo[BATCH * SEQ * HEAD];
__device__ __nv_bfloat16 g_vhi[BATCH * SEQ * HEAD];
__device__ __nv_bfloat16 g_vlo[BATCH * SEQ * HEAD];

// W^T hi/lo: [n=192][k=1024]
__device__ __nv_bfloat16 g_wthi[192 * 1024];
__device__ __nv_bfloat16 g_wtlo[192 * 1024];

// ===========================================================================
// helpers
// ===========================================================================
__device__ __forceinline__ uint32_t smem_u32(const void* p) {
    uint32_t a;
    asm("{ .reg .u64 t; cvta.to.shared.u64 t, %1; cvt.u32.u64 %0, t; }"
        : "=r"(a) : "l"(p));
    return a;
}

__device__ __forceinline__ void ldsm4(uint32_t addr, uint32_t* r) {
    asm volatile("ldmatrix.sync.aligned.m8n8.x4.shared.b16 {%0,%1,%2,%3}, [%4];"
        : "=r"(r[0]), "=r"(r[1]), "=r"(r[2]), "=r"(r[3]) : "r"(addr));
}
__device__ __forceinline__ void ldsm4t(uint32_t addr, uint32_t* r) {
    asm volatile("ldmatrix.sync.aligned.m8n8.x4.trans.shared.b16 {%0,%1,%2,%3}, [%4];"
        : "=r"(r[0]), "=r"(r[1]), "=r"(r[2]), "=r"(r[3]) : "r"(addr));
}

__device__ __forceinline__ void mma16816(float* c, const uint32_t* a,
                                         uint32_t b0, uint32_t b1) {
    asm volatile(
        "mma.sync.aligned.m16n8k16.row.col.f32.bf16.bf16.f32 "
        "{%0,%1,%2,%3}, {%4,%5,%6,%7}, {%8,%9}, {%0,%1,%2,%3};"
        : "+f"(c[0]), "+f"(c[1]), "+f"(c[2]), "+f"(c[3])
        : "r"(a[0]), "r"(a[1]), "r"(a[2]), "r"(a[3]), "r"(b0), "r"(b1));
}

__device__ __forceinline__ void cp_async16(uint32_t saddr, const void* gaddr) {
    asm volatile("cp.async.cg.shared.global [%0], [%1], 16;"
        :: "r"(saddr), "l"(gaddr) : "memory");
}
#define CP_COMMIT() asm volatile("cp.async.commit_group;" ::: "memory")

#define STS128(r0, r1, r2, r3, addr) \
    asm volatile("st.shared.v4.b32 [%0], {%1, %2, %3, %4};" \
        :: "r"(addr), "r"(r0), "r"(r1), "r"(r2), "r"(r3) : "memory")

#define BARPAIR(id) asm volatile("bar.sync %0, 64;" :: "r"(id) : "memory")

__device__ __forceinline__ uint32_t pack2(__nv_bfloat16 lo, __nv_bfloat16 hi) {
    return (uint32_t)__bfloat16_as_ushort(lo) |
           ((uint32_t)__bfloat16_as_ushort(hi) << 16);
}

__device__ __forceinline__ void split2(float x0, float x1,
                                       uint32_t& hw, uint32_t& lw) {
    __nv_bfloat16 h0 = __float2bfloat16(x0);
    __nv_bfloat16 h1 = __float2bfloat16(x1);
    float l0 = x0 - __bfloat162float(h0);
    float l1 = x1 - __bfloat162float(h1);
    hw = pack2(h0, h1);
    lw = pack2(__float2bfloat16(l0), __float2bfloat16(l1));
}

// ===========================================================================
// Kernel 0: W^T hi/lo precompute
// ===========================================================================
__global__ __launch_bounds__(256) void wconv_kernel(
    const float* __restrict__ Wq, const float* __restrict__ Wk,
    const float* __restrict__ Wv)
{
    const int n = blockIdx.x;
    const float* W;
    int nn;
    if (n < 64)       { W = Wq; nn = n; }
    else if (n < 128) { W = Wk; nn = n - 64; }
    else              { W = Wv; nn = n - 128; }
    for (int k = threadIdx.x; k < 1024; k += 256) {
        float v = W[(size_t)k * HEAD + nn];
        __nv_bfloat16 h = __float2bfloat16(v);
        float l = v - __bfloat162float(h);
        g_wthi[(size_t)n * 1024 + k] = h;
        g_wtlo[(size_t)n * 1024 + k] = __float2bfloat16(l);
    }
}

// ===========================================================================
// Kernel 1: QKV projection on mma.sync (3xBF16) — unchanged from R6 pass.
// ===========================================================================
#define QK_STG  92160
#define QX_HI   0
#define QX_LO   18432
#define QW_HI   36864
#define QW_LO   64512
#define QK_SMEM (2 * QK_STG)
#define NCH     (EMB / 64)

__global__ __launch_bounds__(256) void qkv_mma_kernel(
    const float* __restrict__ x,
    const float* __restrict__ bq, const float* __restrict__ bk,
    const float* __restrict__ bv)
{
    extern __shared__ char smem[];
    const uint32_t sbase = smem_u32(smem);
    const int tid  = threadIdx.x;
    const int warp = tid >> 5;
    const int lane = tid & 31;
    const int g    = lane >> 2;
    const int qr   = lane & 3;
    const int warpM = warp >> 1;
    const int warpN = warp & 1;
    const int m0 = blockIdx.x * 128;

    float xr[32];

    auto ldX = [&](int c) {
        const float4* src = reinterpret_cast<const float4*>(
            x + (size_t)(m0 + (tid >> 1)) * EMB + c * 64 + (tid & 1) * 32);
#pragma unroll
        for (int j = 0; j < 8; j++) {
            float4 v = src[j];
            xr[j * 4 + 0] = v.x; xr[j * 4 + 1] = v.y;
            xr[j * 4 + 2] = v.z; xr[j * 4 + 3] = v.w;
        }
    };

    auto stX = [&](int s) {
        const uint32_t dst = sbase + s * QK_STG
            + (uint32_t)(tid >> 1) * 144 + (tid & 1) * 64;
#pragma unroll
        for (int j = 0; j < 4; j++) {
            uint32_t hw[4], lw[4];
#pragma unroll
            for (int p = 0; p < 4; p++)
                split2(xr[j * 8 + p * 2], xr[j * 8 + p * 2 + 1], hw[p], lw[p]);
            STS128(hw[0], hw[1], hw[2], hw[3], dst + QX_HI + j * 16);
            STS128(lw[0], lw[1], lw[2], lw[3], dst + QX_LO + j * 16);
        }
    };

    auto cpW = [&](int c, int s) {
        const uint32_t base = sbase + s * QK_STG;
#pragma unroll
        for (int t = 0; t < 12; t++) {
            const int i   = tid + t * 256;
            const int arr = (i >= 1536) ? 1 : 0;
            const int i2  = arr ? (i - 1536) : i;
            const int row = i2 >> 3, ch = i2 & 7;
            const __nv_bfloat16* src = (arr ? g_wtlo : g_wthi)
                + (size_t)row * 1024 + c * 64 + ch * 8;
            cp_async16(base + (arr ? QW_LO : QW_HI) + row * 144 + ch * 16, src);
        }
        CP_COMMIT();
    };

    float acc[2][12][4];
#pragma unroll
    for (int mt = 0; mt < 2; mt++)
#pragma unroll
        for (int nt = 0; nt < 12; nt++)
#pragma unroll
            for (int e = 0; e < 4; e++) acc[mt][nt][e] = 0.0f;

    ldX(0);
    cpW(0, 0);

    for (int c = 0; c < NCH; c++) {
        const int s = c & 1;
        __syncthreads();
        stX(s);
        if (c + 1 < NCH) {
            cpW(c + 1, s ^ 1);
            asm volatile("cp.async.wait_group 1;" ::: "memory");
        } else {
            asm volatile("cp.async.wait_group 0;" ::: "memory");
        }
        __syncthreads();
        if (c + 1 < NCH) ldX(c + 1);

        const uint32_t xb = sbase + s * QK_STG + QX_HI
            + (uint32_t)(warpM * 32 + (lane & 15)) * 144 + (lane >> 4) * 16;
        const uint32_t wb = sbase + s * QK_STG + QW_HI
            + (uint32_t)(warpN * 96 + ((lane >> 4) & 1) * 8 + (lane & 7)) * 144
            + ((lane >> 3) & 1) * 16;

#pragma unroll
        for (int kc = 0; kc < 4; kc++) {
            uint32_t ah0[4], ah1[4], al0[4], al1[4];
            ldsm4(xb + kc * 32, ah0);
            ldsm4(xb + 16 * 144 + kc * 32, ah1);
            ldsm4(xb + (QX_LO - QX_HI) + kc * 32, al0);
            ldsm4(xb + (QX_LO - QX_HI) + 16 * 144 + kc * 32, al1);
#pragma unroll
            for (int nt = 0; nt < 6; nt++) {
                uint32_t bh[4], bl[4];
                ldsm4(wb + nt * (16 * 144) + kc * 32, bh);
                ldsm4(wb + (QW_LO - QW_HI) + nt * (16 * 144) + kc * 32, bl);
                mma16816(acc[0][2 * nt],     ah0, bh[0], bh[1]);
                mma16816(acc[0][2 * nt],     ah0, bl[0], bl[1]);
                mma16816(acc[0][2 * nt],     al0, bh[0], bh[1]);
                mma16816(acc[0][2 * nt + 1], ah0, bh[2], bh[3]);
                mma16816(acc[0][2 * nt + 1], ah0, bl[2], bl[3]);
                mma16816(acc[0][2 * nt + 1], al0, bh[2], bh[3]);
                mma16816(acc[1][2 * nt],     ah1, bh[0], bh[1]);
                mma16816(acc[1][2 * nt],     ah1, bl[0], bl[1]);
                mma16816(acc[1][2 * nt],     al1, bh[0], bh[1]);
                mma16816(acc[1][2 * nt + 1], ah1, bh[2], bh[3]);
                mma16816(acc[1][2 * nt + 1], ah1, bl[2], bl[3]);
                mma16816(acc[1][2 * nt + 1], al1, bh[2], bh[3]);
            }
        }
    }

#pragma unroll
    for (int mt = 0; mt < 2; mt++) {
        const int rbase = m0 + warpM * 32 + mt * 16 + g;
#pragma unroll
        for (int nt = 0; nt < 12; nt++) {
            const int cc = warpN * 96 + nt * 8 + qr * 2;
#pragma unroll
            for (int half = 0; half < 2; half++) {
                const int r = rbase + half * 8;
                float a0 = acc[mt][nt][half * 2 + 0];
                float a1 = acc[mt][nt][half * 2 + 1];
                __nv_bfloat16 *hiA, *loA;
                int col;
                if (cc < 64) {
                    col = cc;
                    a0 = (a0 + bq[col]) * 0.125f;
                    a1 = (a1 + bq[col + 1]) * 0.125f;
                    hiA = g_qhi; loA = g_qlo;
                } else if (cc < 128) {
                    col = cc - 64;
                    a0 += bk[col]; a1 += bk[col + 1];
                    hiA = g_khi; loA = g_klo;
                } else {
                    col = cc - 128;
                    a0 += bv[col]; a1 += bv[col + 1];
                    hiA = g_vhi; loA = g_vlo;
                }
                uint32_t hw, lw;
                split2(a0, a1, hw, lw);
                const size_t idx = (size_t)r * HEAD + col;
                *reinterpret_cast<uint32_t*>(hiA + idx) = hw;
                *reinterpret_cast<uint32_t*>(loA + idx) = lw;
            }
        }
    }
}

// ===========================================================================
// Kernel 2: flash attention, 8 warps/CTA (warp pair splits key columns).
// warp = (cw<<2)|r : r owns q-rows 16r..16r+15, cw owns key cols cw*32..+31.
// ===========================================================================
#define BQ 64
#define BK 64
#define STRIDE 144

#define SM_QHI   0
#define SM_QLO   9216
#define SM_STAGE 18432
#define STAGE_SZ 36864
#define OFF_KHI  0
#define OFF_KLO  9216
#define OFF_VHI  18432
#define OFF_VLO  27648
#define SM_RED   (SM_STAGE + 2 * STAGE_SZ)        // 92160: [par][max/sum][cw][64] f32
#define SM_TOTAL_A (SM_RED + 2048)                // 94208

__global__ __launch_bounds__(256, 2) void attn_mma_kernel(float* __restrict__ out)
{
    extern __shared__ char smem[];
    const uint32_t sbase = smem_u32(smem);

    const int u  = blockIdx.x;
    const int b  = u & 3;
    const int v_ = u >> 2;
    const int qt = (v_ & 1) ? (63 - (v_ >> 1)) : (v_ >> 1);
    const int q0 = qt * BQ;
    const int nk = qt + 1;

    const int tid  = threadIdx.x;
    const int warp = tid >> 5;
    const int lane = tid & 31;
    const int g    = lane >> 2;
    const int qr   = lane & 3;
    const int r    = warp & 3;
    const int cw   = warp >> 2;
    const int R    = r * 16;
    const int C    = cw * 32;      // this warp's key-column half

    auto prefetch = [&](int kt, int stage) {
        const uint32_t sb = sbase + SM_STAGE + stage * STAGE_SZ;
        const size_t gro = (size_t)(b * SEQ) + (size_t)kt * BK;
#pragma unroll
        for (int t = 0; t < 8; t++) {
            const int i   = tid + t * 256;
            const int arr = i >> 9;
            const int rem = i & 511;
            const int rr = rem >> 3, c = rem & 7;
            const __nv_bfloat16* base;
            uint32_t off;
            if (arr == 0)      { base = g_khi; off = OFF_KHI; }
            else if (arr == 1) { base = g_klo; off = OFF_KLO; }
            else if (arr == 2) { base = g_vhi; off = OFF_VHI; }
            else               { base = g_vlo; off = OFF_VLO; }
            cp_async16(sb + off + rr * STRIDE + c * 16,
                       base + (gro + rr) * HEAD + c * 8);
        }
        CP_COMMIT();
    };

    prefetch(0, 0);

    for (int i = tid; i < 1024; i += 256) {
        const int arr = i >> 9;
        const int rem = i & 511;
        const int rr = rem >> 3, c = rem & 7;
        const __nv_bfloat16* src = (arr == 0 ? g_qhi : g_qlo)
            + ((size_t)(b * SEQ) + q0 + rr) * HEAD + c * 8;
        const int4 val = *reinterpret_cast<const int4*>(src);
        *reinterpret_cast<int4*>(smem + (arr == 0 ? SM_QHI : SM_QLO)
                                 + rr * STRIDE + c * 16) = val;
    }
    __syncthreads();

    // Q A-fragments (rows R..R+15), hi + lo
    const uint32_t aQ = sbase + SM_QHI
        + (uint32_t)(R + (lane & 15)) * STRIDE + ((lane >> 4) * 8) * 2;
    uint32_t qahi[4][4], qalo[4][4];
#pragma unroll
    for (int kc = 0; kc < 4; kc++) {
        ldsm4(aQ + kc * 32, qahi[kc]);
        ldsm4(aQ + 9216 + kc * 32, qalo[kc]);
    }

    // lane-relative ldmatrix offsets within a stage, with cw col-half folded in
    const uint32_t oK = (uint32_t)(C + ((lane >> 4) & 1) * 8 + (lane & 7)) * STRIDE
        + (((lane >> 3) & 1) * 8) * 2;
    const uint32_t oV = (uint32_t)(C + ((lane >> 3) & 1) * 8 + (lane & 7)) * STRIDE
        + (((lane >> 4) & 1) * 8) * 2;

    float oacc[8][4];   // k-partial O over this warp's 32 keys (full 64 cols)
#pragma unroll
    for (int nt = 0; nt < 8; nt++)
#pragma unroll
        for (int e = 0; e < 4; e++) oacc[nt][e] = 0.0f;
    float mr0 = -1e30f, mr1 = -1e30f, l0 = 0.0f, l1 = 0.0f;

    const int barid = 1 + r;

    for (int kt = 0; kt < nk; kt++) {
        __syncthreads();
        if (kt + 1 < nk) {
            prefetch(kt + 1, (kt + 1) & 1);
            asm volatile("cp.async.wait_group 1;" ::: "memory");
        } else {
            asm volatile("cp.async.wait_group 0;" ::: "memory");
        }
        __syncthreads();

        const uint32_t sb = sbase + SM_STAGE + (kt & 1) * STAGE_SZ;
        const uint32_t bK = sb + OFF_KHI + oK;
        const uint32_t bV = sb + OFF_VHI + oV;

        // ---- S (16 rows x 32 cols): hi*hi + hi*lo + lo*hi ----
        float sacc[4][4];
#pragma unroll
        for (int nt = 0; nt < 4; nt++)
#pragma unroll
            for (int e = 0; e < 4; e++) sacc[nt][e] = 0.0f;

#pragma unroll
        for (int kc = 0; kc < 4; kc++) {
#pragma unroll
            for (int npl = 0; npl < 2; npl++) {
                uint32_t bh[4], bl[4];
                ldsm4(bK + npl * (16 * STRIDE) + kc * 32, bh);
                ldsm4(bK + 9216 + npl * (16 * STRIDE) + kc * 32, bl);
                mma16816(sacc[2 * npl],     qahi[kc], bh[0], bh[1]);
                mma16816(sacc[2 * npl],     qahi[kc], bl[0], bl[1]);
                mma16816(sacc[2 * npl],     qalo[kc], bh[0], bh[1]);
                mma16816(sacc[2 * npl + 1], qahi[kc], bh[2], bh[3]);
                mma16816(sacc[2 * npl + 1], qahi[kc], bl[2], bl[3]);
                mma16816(sacc[2 * npl + 1], qalo[kc], bh[2], bh[3]);
            }
        }

        // ---- causal mask (diagonal tile) ----
        if (kt == qt) {
            const int lr0 = R + g, lr1 = R + g + 8;
#pragma unroll
            for (int nt = 0; nt < 4; nt++) {
                const int lc = C + nt * 8 + qr * 2;
                if (lc > lr0)     sacc[nt][0] = -1e30f;
                if (lc + 1 > lr0) sacc[nt][1] = -1e30f;
                if (lc > lr1)     sacc[nt][2] = -1e30f;
                if (lc + 1 > lr1) sacc[nt][3] = -1e30f;
            }
        }

        // ---- partial row max over this warp's 32 cols ----
        float m0 = -1e30f, m1 = -1e30f;
#pragma unroll
        for (int nt = 0; nt < 4; nt++) {
            m0 = fmaxf(m0, fmaxf(sacc[nt][0], sacc[nt][1]));
            m1 = fmaxf(m1, fmaxf(sacc[nt][2], sacc[nt][3]));
        }
        m0 = fmaxf(m0, __shfl_xor_sync(0xffffffffu, m0, 1));
        m0 = fmaxf(m0, __shfl_xor_sync(0xffffffffu, m0, 2));
        m1 = fmaxf(m1, __shfl_xor_sync(0xffffffffu, m1, 1));
        m1 = fmaxf(m1, __shfl_xor_sync(0xffffffffu, m1, 2));

        // exchange with sibling (warp ^ 4) via parity smem slot
        const uint32_t redp = sbase + SM_RED + (kt & 1) * 1024;
        if (qr == 0) {
            *reinterpret_cast<float*>(smem + (redp - sbase) + cw * 256 + (R + g) * 4)     = m0;
            *reinterpret_cast<float*>(smem + (redp - sbase) + cw * 256 + (R + g + 8) * 4) = m1;
        }
        BARPAIR(barid);
        const float om0 = *reinterpret_cast<float*>(
            smem + (redp - sbase) + (cw ^ 1) * 256 + (R + g) * 4);
        const float om1 = *reinterpret_cast<float*>(
            smem + (redp - sbase) + (cw ^ 1) * 256 + (R + g + 8) * 4);

        const float mn0 = fmaxf(mr0, fmaxf(m0, om0));
        const float mn1 = fmaxf(mr1, fmaxf(m1, om1));
        const float corr0 = __expf(mr0 - mn0);
        const float corr1 = __expf(mr1 - mn1);
        mr0 = mn0; mr1 = mn1;

        // ---- exp + pack P A-fragments (k-dim = this warp's 32 keys) ----
        uint32_t aphi[2][4], aplo[2][4];
        float ps0 = 0.0f, ps1 = 0.0f;
#pragma unroll
        for (int kc2 = 0; kc2 < 2; kc2++) {
            const int ntE = 2 * kc2, ntO = 2 * kc2 + 1;
            float pE0 = __expf(sacc[ntE][0] - mn0);
            float pE1 = __expf(sacc[ntE][1] - mn0);
            float pE2 = __expf(sacc[ntE][2] - mn1);
            float pE3 = __expf(sacc[ntE][3] - mn1);
            float pO0 = __expf(sacc[ntO][0] - mn0);
            float pO1 = __expf(sacc[ntO][1] - mn0);
            float pO2 = __expf(sacc[ntO][2] - mn1);
            float pO3 = __expf(sacc[ntO][3] - mn1);
            ps0 += pE0 + pE1 + pO0 + pO1;
            ps1 += pE2 + pE3 + pO2 + pO3;
            split2(pE0, pE1, aphi[kc2][0], aplo[kc2][0]);
            split2(pE2, pE3, aphi[kc2][1], aplo[kc2][1]);
            split2(pO0, pO1, aphi[kc2][2], aplo[kc2][2]);
            split2(pO2, pO3, aphi[kc2][3], aplo[kc2][3]);
        }
        ps0 += __shfl_xor_sync(0xffffffffu, ps0, 1);
        ps0 += __shfl_xor_sync(0xffffffffu, ps0, 2);
        ps1 += __shfl_xor_sync(0xffffffffu, ps1, 1);
        ps1 += __shfl_xor_sync(0xffffffffu, ps1, 2);

        if (qr == 0) {
            *reinterpret_cast<float*>(smem + (redp - sbase) + 512 + cw * 256 + (R + g) * 4)     = ps0;
            *reinterpret_cast<float*>(smem + (redp - sbase) + 512 + cw * 256 + (R + g + 8) * 4) = ps1;
        }
        BARPAIR(barid);
        const float os0 = *reinterpret_cast<float*>(
            smem + (redp - sbase) + 512 + (cw ^ 1) * 256 + (R + g) * 4);
        const float os1 = *reinterpret_cast<float*>(
            smem + (redp - sbase) + 512 + (cw ^ 1) * 256 + (R + g + 8) * 4);

        l0 = l0 * corr0 + ps0 + os0;
        l1 = l1 * corr1 + ps1 + os1;

        // ---- rescale O partials ----
#pragma unroll
        for (int nt = 0; nt < 8; nt++) {
            oacc[nt][0] *= corr0; oacc[nt][1] *= corr0;
            oacc[nt][2] *= corr1; oacc[nt][3] *= corr1;
        }

        // ---- O_partial += P(16x32) * V(32x64) ----
#pragma unroll
        for (int kc2 = 0; kc2 < 2; kc2++) {
#pragma unroll
            for (int np = 0; np < 4; np++) {
                uint32_t bvh[4], bvl[4];
                ldsm4t(bV + kc2 * (16 * STRIDE) + np * 32, bvh);
                ldsm4t(bV + 9216 + kc2 * (16 * STRIDE) + np * 32, bvl);
                mma16816(oacc[2 * np],     aphi[kc2], bvh[0], bvh[1]);
                mma16816(oacc[2 * np],     aphi[kc2], bvl[0], bvl[1]);
                mma16816(oacc[2 * np],     aplo[kc2], bvh[0], bvh[1]);
                mma16816(oacc[2 * np + 1], aphi[kc2], bvh[2], bvh[3]);
                mma16816(oacc[2 * np + 1], aphi[kc2], bvl[2], bvl[3]);
                mma16816(oacc[2 * np + 1], aplo[kc2], bvh[2], bvh[3]);
            }
        }
    }

    // ---- epilogue: merge the two k-partials, normalize, write ----
    __syncthreads();    // all warps done with K/V stages before reuse as O buffer
    float* smO = reinterpret_cast<float*>(smem + SM_STAGE);   // [64][64]
    if (cw == 1) {
#pragma unroll
        for (int nt = 0; nt < 8; nt++) {
            const int col = nt * 8 + qr * 2;
            smO[(R + g) * 64 + col]           = oacc[nt][0];
            smO[(R + g) * 64 + col + 1]       = oacc[nt][1];
            smO[(R + g + 8) * 64 + col]       = oacc[nt][2];
            smO[(R + g + 8) * 64 + col + 1]   = oacc[nt][3];
        }
    }
    __syncthreads();
    if (cw == 0) {
        const float inv0 = 1.0f / l0;
        const float inv1 = 1.0f / l1;
        const size_t row0 = (size_t)(b * SEQ) + q0 + R + g;
        const size_t row1 = row0 + 8;
#pragma unroll
        for (int nt = 0; nt < 8; nt++) {
            const int col = nt * 8 + qr * 2;
            float2 o0;
            o0.x = (oacc[nt][0] + smO[(R + g) * 64 + col]) * inv0;
            o0.y = (oacc[nt][1] + smO[(R + g) * 64 + col + 1]) * inv0;
            float2 o1;
            o1.x = (oacc[nt][2] + smO[(R + g + 8) * 64 + col]) * inv1;
            o1.y = (oacc[nt][3] + smO[(R + g + 8) * 64 + col + 1]) * inv1;
            *reinterpret_cast<float2*>(out + row0 * HEAD + col) = o0;
            *reinterpret_cast<float2*>(out + row1 * HEAD + col) = o1;
        }
    }
}

// ===========================================================================
extern "C" void kernel_launch(void* const* d_in, const int* in_sizes, int n_in,
                              void* d_out, int out_size)
{
    const float* x  = (const float*)d_in[0];
    const float* Wq = (const float*)d_in[1];
    const float* bq = (const float*)d_in[2];
    const float* Wk = (const float*)d_in[3];
    const float* bk = (const float*)d_in[4];
    const float* Wv = (const float*)d_in[5];
    const float* bv = (const float*)d_in[6];
    float* out = (float*)d_out;

    wconv_kernel<<<192, 256>>>(Wq, Wk, Wv);

    {
        cudaFuncSetAttribute(qkv_mma_kernel,
                             cudaFuncAttributeMaxDynamicSharedMemorySize, QK_SMEM);
        qkv_mma_kernel<<<128, 256, QK_SMEM>>>(x, bq, bk, bv);
    }

    {
        cudaFuncSetAttribute(attn_mma_kernel,
                             cudaFuncAttributeMaxDynamicSharedMemorySize, SM_TOTAL_A);
        attn_mma_kernel<<<256, 256, SM_TOTAL_A>>>(out);
    }
}

// round 8
// speedup vs baseline: 3.9631x; 1.0952x over previous
#include <cuda_runtime.h>
#include <cuda_bf16.h>
#include <math.h>
#include <cstdint>

#define BATCH 4
#define SEQ   4096
#define EMB   1024
#define HEAD  64

// bf16 hi/lo split of projected q (pre-scaled by 0.125), k, v. 2 MB each.
__device__ __nv_bfloat16 g_qhi[BATCH * SEQ * HEAD];
__device__ __nv_bfloat16 g_qlo[BATCH * SEQ * HEAD];
__device__ __nv_bfloat16 g_khi[BATCH * SEQ * HEAD];
__device__ __nv_bfloat16 g_klo[BATCH * SEQ * HEAD];
__device__ __nv_bfloat16 g_vhi[BATCH * SEQ * HEAD];
__device__ __nv_bfloat16 g_vlo[BATCH * SEQ * HEAD];

// W^T hi/lo: [n=192][k=1024]
__device__ __nv_bfloat16 g_wthi[192 * 1024];
__device__ __nv_bfloat16 g_wtlo[192 * 1024];

// split-K partials: [b][qt][s<=4][64 rows][64 cols] and m/l per row
__device__ float g_opart[BATCH * 64 * 4 * 64 * 64];   // 16 MB
__device__ float g_mpart[BATCH * 64 * 4 * 64];
__device__ float g_lpart[BATCH * 64 * 4 * 64];

// ===========================================================================
// helpers
// ===========================================================================
__device__ __forceinline__ uint32_t smem_u32(const void* p) {
    uint32_t a;
    asm("{ .reg .u64 t; cvta.to.shared.u64 t, %1; cvt.u32.u64 %0, t; }"
        : "=r"(a) : "l"(p));
    return a;
}

__device__ __forceinline__ void ldsm4(uint32_t addr, uint32_t* r) {
    asm volatile("ldmatrix.sync.aligned.m8n8.x4.shared.b16 {%0,%1,%2,%3}, [%4];"
        : "=r"(r[0]), "=r"(r[1]), "=r"(r[2]), "=r"(r[3]) : "r"(addr));
}
__device__ __forceinline__ void ldsm4t(uint32_t addr, uint32_t* r) {
    asm volatile("ldmatrix.sync.aligned.m8n8.x4.trans.shared.b16 {%0,%1,%2,%3}, [%4];"
        : "=r"(r[0]), "=r"(r[1]), "=r"(r[2]), "=r"(r[3]) : "r"(addr));
}

__device__ __forceinline__ void mma16816(float* c, const uint32_t* a,
                                         uint32_t b0, uint32_t b1) {
    asm volatile(
        "mma.sync.aligned.m16n8k16.row.col.f32.bf16.bf16.f32 "
        "{%0,%1,%2,%3}, {%4,%5,%6,%7}, {%8,%9}, {%0,%1,%2,%3};"
        : "+f"(c[0]), "+f"(c[1]), "+f"(c[2]), "+f"(c[3])
        : "r"(a[0]), "r"(a[1]), "r"(a[2]), "r"(a[3]), "r"(b0), "r"(b1));
}

__device__ __forceinline__ void cp_async16(uint32_t saddr, const void* gaddr) {
    asm volatile("cp.async.cg.shared.global [%0], [%1], 16;"
        :: "r"(saddr), "l"(gaddr) : "memory");
}
#define CP_COMMIT() asm volatile("cp.async.commit_group;" ::: "memory")

#define STS128(r0, r1, r2, r3, addr) \
    asm volatile("st.shared.v4.b32 [%0], {%1, %2, %3, %4};" \
        :: "r"(addr), "r"(r0), "r"(r1), "r"(r2), "r"(r3) : "memory")

__device__ __forceinline__ uint32_t pack2(__nv_bfloat16 lo, __nv_bfloat16 hi) {
    return (uint32_t)__bfloat16_as_ushort(lo) |
           ((uint32_t)__bfloat16_as_ushort(hi) << 16);
}

__device__ __forceinline__ void split2(float x0, float x1,
                                       uint32_t& hw, uint32_t& lw) {
    __nv_bfloat16 h0 = __float2bfloat16(x0);
    __nv_bfloat16 h1 = __float2bfloat16(x1);
    float l0 = x0 - __bfloat162float(h0);
    float l1 = x1 - __bfloat162float(h1);
    hw = pack2(h0, h1);
    lw = pack2(__float2bfloat16(l0), __float2bfloat16(l1));
}

// ===========================================================================
// Kernel 0: W^T hi/lo precompute
// ===========================================================================
__global__ __launch_bounds__(256) void wconv_kernel(
    const float* __restrict__ Wq, const float* __restrict__ Wk,
    const float* __restrict__ Wv)
{
    const int n = blockIdx.x;
    const float* W;
    int nn;
    if (n < 64)       { W = Wq; nn = n; }
    else if (n < 128) { W = Wk; nn = n - 64; }
    else              { W = Wv; nn = n - 128; }
    for (int k = threadIdx.x; k < 1024; k += 256) {
        float v = W[(size_t)k * HEAD + nn];
        __nv_bfloat16 h = __float2bfloat16(v);
        float l = v - __bfloat162float(h);
        g_wthi[(size_t)n * 1024 + k] = h;
        g_wtlo[(size_t)n * 1024 + k] = __float2bfloat16(l);
    }
}

// ===========================================================================
// Kernel 1: QKV projection on mma.sync (3xBF16) — unchanged (R6 pass).
// ===========================================================================
#define QK_STG  92160
#define QX_HI   0
#define QX_LO   18432
#define QW_HI   36864
#define QW_LO   64512
#define QK_SMEM (2 * QK_STG)
#define NCH     (EMB / 64)

__global__ __launch_bounds__(256) void qkv_mma_kernel(
    const float* __restrict__ x,
    const float* __restrict__ bq, const float* __restrict__ bk,
    const float* __restrict__ bv)
{
    extern __shared__ char smem[];
    const uint32_t sbase = smem_u32(smem);
    const int tid  = threadIdx.x;
    const int warp = tid >> 5;
    const int lane = tid & 31;
    const int g    = lane >> 2;
    const int qr   = lane & 3;
    const int warpM = warp >> 1;
    const int warpN = warp & 1;
    const int m0 = blockIdx.x * 128;

    float xr[32];

    auto ldX = [&](int c) {
        const float4* src = reinterpret_cast<const float4*>(
            x + (size_t)(m0 + (tid >> 1)) * EMB + c * 64 + (tid & 1) * 32);
#pragma unroll
        for (int j = 0; j < 8; j++) {
            float4 v = src[j];
            xr[j * 4 + 0] = v.x; xr[j * 4 + 1] = v.y;
            xr[j * 4 + 2] = v.z; xr[j * 4 + 3] = v.w;
        }
    };

    auto stX = [&](int s) {
        const uint32_t dst = sbase + s * QK_STG
            + (uint32_t)(tid >> 1) * 144 + (tid & 1) * 64;
#pragma unroll
        for (int j = 0; j < 4; j++) {
            uint32_t hw[4], lw[4];
#pragma unroll
            for (int p = 0; p < 4; p++)
                split2(xr[j * 8 + p * 2], xr[j * 8 + p * 2 + 1], hw[p], lw[p]);
            STS128(hw[0], hw[1], hw[2], hw[3], dst + QX_HI + j * 16);
            STS128(lw[0], lw[1], lw[2], lw[3], dst + QX_LO + j * 16);
        }
    };

    auto cpW = [&](int c, int s) {
        const uint32_t base = sbase + s * QK_STG;
#pragma unroll
        for (int t = 0; t < 12; t++) {
            const int i   = tid + t * 256;
            const int arr = (i >= 1536) ? 1 : 0;
            const int i2  = arr ? (i - 1536) : i;
            const int row = i2 >> 3, ch = i2 & 7;
            const __nv_bfloat16* src = (arr ? g_wtlo : g_wthi)
                + (size_t)row * 1024 + c * 64 + ch * 8;
            cp_async16(base + (arr ? QW_LO : QW_HI) + row * 144 + ch * 16, src);
        }
        CP_COMMIT();
    };

    float acc[2][12][4];
#pragma unroll
    for (int mt = 0; mt < 2; mt++)
#pragma unroll
        for (int nt = 0; nt < 12; nt++)
#pragma unroll
            for (int e = 0; e < 4; e++) acc[mt][nt][e] = 0.0f;

    ldX(0);
    cpW(0, 0);

    for (int c = 0; c < NCH; c++) {
        const int s = c & 1;
        __syncthreads();
        stX(s);
        if (c + 1 < NCH) {
            cpW(c + 1, s ^ 1);
            asm volatile("cp.async.wait_group 1;" ::: "memory");
        } else {
            asm volatile("cp.async.wait_group 0;" ::: "memory");
        }
        __syncthreads();
        if (c + 1 < NCH) ldX(c + 1);

        const uint32_t xb = sbase + s * QK_STG + QX_HI
            + (uint32_t)(warpM * 32 + (lane & 15)) * 144 + (lane >> 4) * 16;
        const uint32_t wb = sbase + s * QK_STG + QW_HI
            + (uint32_t)(warpN * 96 + ((lane >> 4) & 1) * 8 + (lane & 7)) * 144
            + ((lane >> 3) & 1) * 16;

#pragma unroll
        for (int kc = 0; kc < 4; kc++) {
            uint32_t ah0[4], ah1[4], al0[4], al1[4];
            ldsm4(xb + kc * 32, ah0);
            ldsm4(xb + 16 * 144 + kc * 32, ah1);
            ldsm4(xb + (QX_LO - QX_HI) + kc * 32, al0);
            ldsm4(xb + (QX_LO - QX_HI) + 16 * 144 + kc * 32, al1);
#pragma unroll
            for (int nt = 0; nt < 6; nt++) {
                uint32_t bh[4], bl[4];
                ldsm4(wb + nt * (16 * 144) + kc * 32, bh);
                ldsm4(wb + (QW_LO - QW_HI) + nt * (16 * 144) + kc * 32, bl);
                mma16816(acc[0][2 * nt],     ah0, bh[0], bh[1]);
                mma16816(acc[0][2 * nt],     ah0, bl[0], bl[1]);
                mma16816(acc[0][2 * nt],     al0, bh[0], bh[1]);
                mma16816(acc[0][2 * nt + 1], ah0, bh[2], bh[3]);
                mma16816(acc[0][2 * nt + 1], ah0, bl[2], bl[3]);
                mma16816(acc[0][2 * nt + 1], al0, bh[2], bh[3]);
                mma16816(acc[1][2 * nt],     ah1, bh[0], bh[1]);
                mma16816(acc[1][2 * nt],     ah1, bl[0], bl[1]);
                mma16816(acc[1][2 * nt],     al1, bh[0], bh[1]);
                mma16816(acc[1][2 * nt + 1], ah1, bh[2], bh[3]);
                mma16816(acc[1][2 * nt + 1], ah1, bl[2], bl[3]);
                mma16816(acc[1][2 * nt + 1], al1, bh[2], bh[3]);
            }
        }
    }

#pragma unroll
    for (int mt = 0; mt < 2; mt++) {
        const int rbase = m0 + warpM * 32 + mt * 16 + g;
#pragma unroll
        for (int nt = 0; nt < 12; nt++) {
            const int cc = warpN * 96 + nt * 8 + qr * 2;
#pragma unroll
            for (int half = 0; half < 2; half++) {
                const int r = rbase + half * 8;
                float a0 = acc[mt][nt][half * 2 + 0];
                float a1 = acc[mt][nt][half * 2 + 1];
                __nv_bfloat16 *hiA, *loA;
                int col;
                if (cc < 64) {
                    col = cc;
                    a0 = (a0 + bq[col]) * 0.125f;
                    a1 = (a1 + bq[col + 1]) * 0.125f;
                    hiA = g_qhi; loA = g_qlo;
                } else if (cc < 128) {
                    col = cc - 64;
                    a0 += bk[col]; a1 += bk[col + 1];
                    hiA = g_khi; loA = g_klo;
                } else {
                    col = cc - 128;
                    a0 += bv[col]; a1 += bv[col + 1];
                    hiA = g_vhi; loA = g_vlo;
                }
                uint32_t hw, lw;
                split2(a0, a1, hw, lw);
                const size_t idx = (size_t)r * HEAD + col;
                *reinterpret_cast<uint32_t*>(hiA + idx) = hw;
                *reinterpret_cast<uint32_t*>(loA + idx) = lw;
            }
        }
    }
}

// ===========================================================================
// Kernel 2: split-K flash attention (R4 4-warp body + k-chunking).
// Grid: 640 chunks. nsp(qt) = (qt>>4)+1 chunks per (b,qt), chunk <= 16 tiles.
// ===========================================================================
#define BQ 64
#define BK 64
#define STRIDE 144

#define SM_QHI   0
#define SM_QLO   9216
#define SM_STAGE 18432
#define STAGE_SZ 36864
#define OFF_KHI  0
#define OFF_KLO  9216
#define OFF_VHI  18432
#define OFF_VLO  27648
#define SM_TOTAL (SM_STAGE + 2 * STAGE_SZ)   // 92160

#define ATTN_GRID (BATCH * 160)              // 640

__global__ __launch_bounds__(128) void attn_mma_kernel(float* __restrict__ out)
{
    extern __shared__ char smem[];
    const uint32_t sbase = smem_u32(smem);

    // decode blockIdx -> (b, qt, s)
    const int b = blockIdx.x & 3;
    int i = blockIdx.x >> 2;        // 0..159
    int qt = 0, s = i;
#pragma unroll 1
    for (qt = 0; qt < 64; qt++) {
        const int c = (qt >> 4) + 1;
        if (s < c) break;
        s -= c;
    }
    const int nk  = qt + 1;
    const int nsp = (qt >> 4) + 1;
    const int chn = (nk + nsp - 1) / nsp;          // chunk length (tiles)
    const int k0  = s * chn;
    const int k1  = (k0 + chn < nk) ? (k0 + chn) : nk;
    const int q0  = qt * BQ;

    const int tid  = threadIdx.x;
    const int warp = tid >> 5;
    const int lane = tid & 31;
    const int g    = lane >> 2;
    const int qr   = lane & 3;
    const int R    = warp * 16;

    auto prefetch = [&](int kt, int stage) {
        const uint32_t sb = sbase + SM_STAGE + stage * STAGE_SZ;
        const size_t gro = (size_t)(b * SEQ) + (size_t)kt * BK;
#pragma unroll
        for (int t = 0; t < 16; t++) {
            const int ii  = tid + t * 128;
            const int arr = ii >> 9;
            const int rem = ii & 511;
            const int r = rem >> 3, c = rem & 7;
            const __nv_bfloat16* base;
            uint32_t off;
            if (arr == 0)      { base = g_khi; off = OFF_KHI; }
            else if (arr == 1) { base = g_klo; off = OFF_KLO; }
            else if (arr == 2) { base = g_vhi; off = OFF_VHI; }
            else               { base = g_vlo; off = OFF_VLO; }
            cp_async16(sb + off + r * STRIDE + c * 16,
                       base + (gro + r) * HEAD + c * 8);
        }
        CP_COMMIT();
    };

    prefetch(k0, 0);

    for (int ii = tid; ii < 1024; ii += 128) {
        const int arr = ii >> 9;
        const int rem = ii & 511;
        const int r = rem >> 3, c = rem & 7;
        const __nv_bfloat16* src = (arr == 0 ? g_qhi : g_qlo)
            + ((size_t)(b * SEQ) + q0 + r) * HEAD + c * 8;
        const int4 val = *reinterpret_cast<const int4*>(src);
        *reinterpret_cast<int4*>(smem + (arr == 0 ? SM_QHI : SM_QLO)
                                 + r * STRIDE + c * 16) = val;
    }
    __syncthreads();

    const uint32_t aQ = sbase + SM_QHI
        + (uint32_t)(R + (lane & 15)) * STRIDE + ((lane >> 4) * 8) * 2;
    uint32_t qahi[4][4], qalo[4][4];
#pragma unroll
    for (int kc = 0; kc < 4; kc++) {
        ldsm4(aQ + kc * 32, qahi[kc]);
        ldsm4(aQ + 9216 + kc * 32, qalo[kc]);
    }

    const uint32_t oK = (uint32_t)(((lane >> 4) & 1) * 8 + (lane & 7)) * STRIDE
        + (((lane >> 3) & 1) * 8) * 2;
    const uint32_t oV = (uint32_t)(((lane >> 3) & 1) * 8 + (lane & 7)) * STRIDE
        + (((lane >> 4) & 1) * 8) * 2;

    float oacc[8][4];
#pragma unroll
    for (int nt = 0; nt < 8; nt++)
#pragma unroll
        for (int e = 0; e < 4; e++) oacc[nt][e] = 0.0f;
    float mr0 = -1e30f, mr1 = -1e30f, l0 = 0.0f, l1 = 0.0f;

    for (int j = 0; j < k1 - k0; j++) {
        const int kt = k0 + j;
        __syncthreads();
        if (kt + 1 < k1) {
            prefetch(kt + 1, (j + 1) & 1);
            asm volatile("cp.async.wait_group 1;" ::: "memory");
        } else {
            asm volatile("cp.async.wait_group 0;" ::: "memory");
        }
        __syncthreads();

        const uint32_t sb = sbase + SM_STAGE + (j & 1) * STAGE_SZ;
        const uint32_t bK = sb + OFF_KHI + oK;
        const uint32_t bV = sb + OFF_VHI + oV;

        float sacc[8][4];
#pragma unroll
        for (int nt = 0; nt < 8; nt++)
#pragma unroll
            for (int e = 0; e < 4; e++) sacc[nt][e] = 0.0f;

#pragma unroll
        for (int kc = 0; kc < 4; kc++) {
#pragma unroll
            for (int np = 0; np < 4; np++) {
                uint32_t bh[4], bl[4];
                ldsm4(bK + np * (16 * STRIDE) + kc * 32, bh);
                ldsm4(bK + 9216 + np * (16 * STRIDE) + kc * 32, bl);
                mma16816(sacc[2 * np],     qahi[kc], bh[0], bh[1]);
                mma16816(sacc[2 * np],     qahi[kc], bl[0], bl[1]);
                mma16816(sacc[2 * np],     qalo[kc], bh[0], bh[1]);
                mma16816(sacc[2 * np + 1], qahi[kc], bh[2], bh[3]);
                mma16816(sacc[2 * np + 1], qahi[kc], bl[2], bl[3]);
                mma16816(sacc[2 * np + 1], qalo[kc], bh[2], bh[3]);
            }
        }

        if (kt == qt) {
            const int lr0 = R + g, lr1 = R + g + 8;
#pragma unroll
            for (int nt = 0; nt < 8; nt++) {
                const int lc = nt * 8 + qr * 2;
                if (lc > lr0)     sacc[nt][0] = -1e30f;
                if (lc + 1 > lr0) sacc[nt][1] = -1e30f;
                if (lc > lr1)     sacc[nt][2] = -1e30f;
                if (lc + 1 > lr1) sacc[nt][3] = -1e30f;
            }
        }

        float m0 = -1e30f, m1 = -1e30f;
#pragma unroll
        for (int nt = 0; nt < 8; nt++) {
            m0 = fmaxf(m0, fmaxf(sacc[nt][0], sacc[nt][1]));
            m1 = fmaxf(m1, fmaxf(sacc[nt][2], sacc[nt][3]));
        }
        m0 = fmaxf(m0, __shfl_xor_sync(0xffffffffu, m0, 1));
        m0 = fmaxf(m0, __shfl_xor_sync(0xffffffffu, m0, 2));
        m1 = fmaxf(m1, __shfl_xor_sync(0xffffffffu, m1, 1));
        m1 = fmaxf(m1, __shfl_xor_sync(0xffffffffu, m1, 2));

        const float mn0 = fmaxf(mr0, m0);
        const float mn1 = fmaxf(mr1, m1);
        const float corr0 = __expf(mr0 - mn0);
        const float corr1 = __expf(mr1 - mn1);
        mr0 = mn0; mr1 = mn1;

        uint32_t aphi[4][4], aplo[4][4];
        float ps0 = 0.0f, ps1 = 0.0f;
#pragma unroll
        for (int kc2 = 0; kc2 < 4; kc2++) {
            const int ntE = 2 * kc2, ntO = 2 * kc2 + 1;
            float pE0 = __expf(sacc[ntE][0] - mn0);
            float pE1 = __expf(sacc[ntE][1] - mn0);
            float pE2 = __expf(sacc[ntE][2] - mn1);
            float pE3 = __expf(sacc[ntE][3] - mn1);
            float pO0 = __expf(sacc[ntO][0] - mn0);
            float pO1 = __expf(sacc[ntO][1] - mn0);
            float pO2 = __expf(sacc[ntO][2] - mn1);
            float pO3 = __expf(sacc[ntO][3] - mn1);
            ps0 += pE0 + pE1 + pO0 + pO1;
            ps1 += pE2 + pE3 + pO2 + pO3;
            split2(pE0, pE1, aphi[kc2][0], aplo[kc2][0]);
            split2(pE2, pE3, aphi[kc2][1], aplo[kc2][1]);
            split2(pO0, pO1, aphi[kc2][2], aplo[kc2][2]);
            split2(pO2, pO3, aphi[kc2][3], aplo[kc2][3]);
        }
        ps0 += __shfl_xor_sync(0xffffffffu, ps0, 1);
        ps0 += __shfl_xor_sync(0xffffffffu, ps0, 2);
        ps1 += __shfl_xor_sync(0xffffffffu, ps1, 1);
        ps1 += __shfl_xor_sync(0xffffffffu, ps1, 2);
        l0 = l0 * corr0 + ps0;
        l1 = l1 * corr1 + ps1;

#pragma unroll
        for (int nt = 0; nt < 8; nt++) {
            oacc[nt][0] *= corr0; oacc[nt][1] *= corr0;
            oacc[nt][2] *= corr1; oacc[nt][3] *= corr1;
        }

#pragma unroll
        for (int kc2 = 0; kc2 < 4; kc2++) {
#pragma unroll
            for (int np = 0; np < 4; np++) {
                uint32_t bvh[4], bvl[4];
                ldsm4t(bV + kc2 * (16 * STRIDE) + np * 32, bvh);
                ldsm4t(bV + 9216 + kc2 * (16 * STRIDE) + np * 32, bvl);
                mma16816(oacc[2 * np],     aphi[kc2], bvh[0], bvh[1]);
                mma16816(oacc[2 * np],     aphi[kc2], bvl[0], bvl[1]);
                mma16816(oacc[2 * np],     aplo[kc2], bvh[0], bvh[1]);
                mma16816(oacc[2 * np + 1], aphi[kc2], bvh[2], bvh[3]);
                mma16816(oacc[2 * np + 1], aphi[kc2], bvl[2], bvl[3]);
                mma16816(oacc[2 * np + 1], aplo[kc2], bvh[2], bvh[3]);
            }
        }
    }

    // ---- epilogue ----
    if (nsp == 1) {
        const float inv0 = 1.0f / l0;
        const float inv1 = 1.0f / l1;
        const size_t row0 = (size_t)(b * SEQ) + q0 + R + g;
        const size_t row1 = row0 + 8;
#pragma unroll
        for (int nt = 0; nt < 8; nt++) {
            const int col = nt * 8 + qr * 2;
            float2 o0; o0.x = oacc[nt][0] * inv0; o0.y = oacc[nt][1] * inv0;
            float2 o1; o1.x = oacc[nt][2] * inv1; o1.y = oacc[nt][3] * inv1;
            *reinterpret_cast<float2*>(out + row0 * HEAD + col) = o0;
            *reinterpret_cast<float2*>(out + row1 * HEAD + col) = o1;
        }
    } else {
        const int pidx = ((b * 64 + qt) * 4 + s);
        float* op = g_opart + (size_t)pidx * 4096;
#pragma unroll
        for (int nt = 0; nt < 8; nt++) {
            const int col = nt * 8 + qr * 2;
            float2 o0; o0.x = oacc[nt][0]; o0.y = oacc[nt][1];
            float2 o1; o1.x = oacc[nt][2]; o1.y = oacc[nt][3];
            *reinterpret_cast<float2*>(op + (R + g) * 64 + col) = o0;
            *reinterpret_cast<float2*>(op + (R + g + 8) * 64 + col) = o1;
        }
        if (qr == 0) {
            g_mpart[pidx * 64 + R + g]     = mr0;
            g_mpart[pidx * 64 + R + g + 8] = mr1;
            g_lpart[pidx * 64 + R + g]     = l0;
            g_lpart[pidx * 64 + R + g + 8] = l1;
        }
    }
}

// ===========================================================================
// Kernel 3: split-K merge. Grid 256 = (b, qt); early-out when nsp==1.
// ===========================================================================
__global__ __launch_bounds__(256) void merge_kernel(float* __restrict__ out)
{
    const int b  = blockIdx.x & 3;
    const int qt = blockIdx.x >> 2;
    const int nsp = (qt >> 4) + 1;
    if (nsp == 1) return;

    const int tid = threadIdx.x;
    const int row = tid >> 2;          // 0..63
    const int cg  = tid & 3;           // 16 cols each

    const int pbase = (b * 64 + qt) * 4;
    float m[4], lv[4];
    float M = -1e30f;
    for (int s = 0; s < nsp; s++) {
        m[s]  = g_mpart[(pbase + s) * 64 + row];
        lv[s] = g_lpart[(pbase + s) * 64 + row];
        M = fmaxf(M, m[s]);
    }
    float w[4];
    float L = 0.0f;
    for (int s = 0; s < nsp; s++) {
        w[s] = __expf(m[s] - M);
        L += lv[s] * w[s];
    }
    const float inv = 1.0f / L;

    float* o = out + ((size_t)(b * SEQ) + qt * 64 + row) * HEAD + cg * 16;
#pragma unroll
    for (int c4 = 0; c4 < 4; c4++) {
        float4 acc = make_float4(0.f, 0.f, 0.f, 0.f);
        for (int s = 0; s < nsp; s++) {
            const float4 v = *reinterpret_cast<const float4*>(
                g_opart + (size_t)(pbase + s) * 4096 + row * 64 + cg * 16 + c4 * 4);
            acc.x += w[s] * v.x; acc.y += w[s] * v.y;
            acc.z += w[s] * v.z; acc.w += w[s] * v.w;
        }
        acc.x *= inv; acc.y *= inv; acc.z *= inv; acc.w *= inv;
        *reinterpret_cast<float4*>(o + c4 * 4) = acc;
    }
}

// ===========================================================================
extern "C" void kernel_launch(void* const* d_in, const int* in_sizes, int n_in,
                              void* d_out, int out_size)
{
    const float* x  = (const float*)d_in[0];
    const float* Wq = (const float*)d_in[1];
    const float* bq = (const float*)d_in[2];
    const float* Wk = (const float*)d_in[3];
    const float* bk = (const float*)d_in[4];
    const float* Wv = (const float*)d_in[5];
    const float* bv = (const float*)d_in[6];
    float* out = (float*)d_out;

    wconv_kernel<<<192, 256>>>(Wq, Wk, Wv);

    {
        cudaFuncSetAttribute(qkv_mma_kernel,
                             cudaFuncAttributeMaxDynamicSharedMemorySize, QK_SMEM);
        qkv_mma_kernel<<<128, 256, QK_SMEM>>>(x, bq, bk, bv);
    }

    {
        cudaFuncSetAttribute(attn_mma_kernel,
                             cudaFuncAttributeMaxDynamicSharedMemorySize, SM_TOTAL);
        attn_mma_kernel<<<ATTN_GRID, 128, SM_TOTAL>>>(out);
    }

    merge_kernel<<<256, 256>>>(out);
}

// round 10
// speedup vs baseline: 4.5619x; 1.1511x over previous
#include <cuda_runtime.h>
#include <cuda_bf16.h>
#include <math.h>
#include <cstdint>

#define BATCH 4
#define SEQ   4096
#define EMB   1024
#define HEAD  64

// bf16 hi/lo split of projected q (pre-scaled by 0.125), k, v. 2 MB each.
__device__ __nv_bfloat16 g_qhi[BATCH * SEQ * HEAD];
__device__ __nv_bfloat16 g_qlo[BATCH * SEQ * HEAD];
__device__ __nv_bfloat16 g_khi[BATCH * SEQ * HEAD];
__device__ __nv_bfloat16 g_klo[BATCH * SEQ * HEAD];
__device__ __nv_bfloat16 g_vhi[BATCH * SEQ * HEAD];
__device__ __nv_bfloat16 g_vlo[BATCH * SEQ * HEAD];

// W^T hi/lo: [n=192][k=1024]
__device__ __nv_bfloat16 g_wthi[192 * 1024];
__device__ __nv_bfloat16 g_wtlo[192 * 1024];

// split-K partials: [b][qt][s<=4][64 rows][64 cols] and m/l per row
__device__ float g_opart[BATCH * 64 * 4 * 64 * 64];   // 16 MB
__device__ float g_mpart[BATCH * 64 * 4 * 64];
__device__ float g_lpart[BATCH * 64 * 4 * 64];

// ===========================================================================
// helpers
// ===========================================================================
__device__ __forceinline__ uint32_t smem_u32(const void* p) {
    uint32_t a;
    asm("{ .reg .u64 t; cvta.to.shared.u64 t, %1; cvt.u32.u64 %0, t; }"
        : "=r"(a) : "l"(p));
    return a;
}

__device__ __forceinline__ void ldsm4(uint32_t addr, uint32_t* r) {
    asm volatile("ldmatrix.sync.aligned.m8n8.x4.shared.b16 {%0,%1,%2,%3}, [%4];"
        : "=r"(r[0]), "=r"(r[1]), "=r"(r[2]), "=r"(r[3]) : "r"(addr));
}
__device__ __forceinline__ void ldsm4t(uint32_t addr, uint32_t* r) {
    asm volatile("ldmatrix.sync.aligned.m8n8.x4.trans.shared.b16 {%0,%1,%2,%3}, [%4];"
        : "=r"(r[0]), "=r"(r[1]), "=r"(r[2]), "=r"(r[3]) : "r"(addr));
}

__device__ __forceinline__ void mma16816(float* c, const uint32_t* a,
                                         uint32_t b0, uint32_t b1) {
    asm volatile(
        "mma.sync.aligned.m16n8k16.row.col.f32.bf16.bf16.f32 "
        "{%0,%1,%2,%3}, {%4,%5,%6,%7}, {%8,%9}, {%0,%1,%2,%3};"
        : "+f"(c[0]), "+f"(c[1]), "+f"(c[2]), "+f"(c[3])
        : "r"(a[0]), "r"(a[1]), "r"(a[2]), "r"(a[3]), "r"(b0), "r"(b1));
}

__device__ __forceinline__ void cp_async16(uint32_t saddr, const void* gaddr) {
    asm volatile("cp.async.cg.shared.global [%0], [%1], 16;"
        :: "r"(saddr), "l"(gaddr) : "memory");
}
#define CP_COMMIT() asm volatile("cp.async.commit_group;" ::: "memory")

#define STS128(r0, r1, r2, r3, addr) \
    asm volatile("st.shared.v4.b32 [%0], {%1, %2, %3, %4};" \
        :: "r"(addr), "r"(r0), "r"(r1), "r"(r2), "r"(r3) : "memory")

__device__ __forceinline__ uint32_t pack2(__nv_bfloat16 lo, __nv_bfloat16 hi) {
    return (uint32_t)__bfloat16_as_ushort(lo) |
           ((uint32_t)__bfloat16_as_ushort(hi) << 16);
}

__device__ __forceinline__ void split2(float x0, float x1,
                                       uint32_t& hw, uint32_t& lw) {
    __nv_bfloat16 h0 = __float2bfloat16(x0);
    __nv_bfloat16 h1 = __float2bfloat16(x1);
    float l0 = x0 - __bfloat162float(h0);
    float l1 = x1 - __bfloat162float(h1);
    hw = pack2(h0, h1);
    lw = pack2(__float2bfloat16(l0), __float2bfloat16(l1));
}

// ===========================================================================
// Kernel 0: W^T hi/lo precompute (coalesced via smem transpose)
// ===========================================================================
__global__ __launch_bounds__(256) void wconv_kernel(
    const float* __restrict__ Wq, const float* __restrict__ Wk,
    const float* __restrict__ Wv)
{
    __shared__ float tile[64][65];
    const int mat = blockIdx.x >> 4;
    const int k0  = (blockIdx.x & 15) * 64;
    const float* W = (mat == 0) ? Wq : ((mat == 1) ? Wk : Wv);

#pragma unroll
    for (int r = 0; r < 64; r += 4) {
        const int k = k0 + r + (threadIdx.x >> 6);
        const int n = threadIdx.x & 63;
        tile[r + (threadIdx.x >> 6)][n] = W[(size_t)k * 64 + n];
    }
    __syncthreads();

    const int n  = threadIdx.x >> 2;
    const int kc = (threadIdx.x & 3) * 16;
    const size_t base = ((size_t)(mat * 64 + n)) * 1024 + k0 + kc;
#pragma unroll
    for (int j = 0; j < 16; j++) {
        const float v = tile[kc + j][n];
        const __nv_bfloat16 h = __float2bfloat16(v);
        g_wthi[base + j] = h;
        g_wtlo[base + j] = __float2bfloat16(v - __bfloat162float(h));
    }
}

// ===========================================================================
// Kernel 1: QKV projection on mma.sync (3xBF16). 512 threads, 16 warps.
// ===========================================================================
#define QK_STG  92160
#define QX_HI   0
#define QX_LO   18432
#define QW_HI   36864
#define QW_LO   64512
#define QK_SMEM (2 * QK_STG)
#define NCH     (EMB / 64)

__global__ __launch_bounds__(512, 1) void qkv_mma_kernel(
    const float* __restrict__ x,
    const float* __restrict__ bq, const float* __restrict__ bk,
    const float* __restrict__ bv)
{
    extern __shared__ char smem[];
    const uint32_t sbase = smem_u32(smem);
    const int tid  = threadIdx.x;
    const int warp = tid >> 5;
    const int lane = tid & 31;
    const int g    = lane >> 2;
    const int qr   = lane & 3;
    const int warpM = warp >> 1;
    const int warpN = warp & 1;
    const int m0 = blockIdx.x * 128;

    const int xrow = tid >> 2;
    const int xq   = (tid & 3) * 16;

    float xr[16];

    auto ldX = [&](int c) {
        const float4* src = reinterpret_cast<const float4*>(
            x + (size_t)(m0 + xrow) * EMB + c * 64 + xq);
#pragma unroll
        for (int j = 0; j < 4; j++) {
            float4 v = src[j];
            xr[j * 4 + 0] = v.x; xr[j * 4 + 1] = v.y;
            xr[j * 4 + 2] = v.z; xr[j * 4 + 3] = v.w;
        }
    };

    auto stX = [&](int s) {
        const uint32_t dst = sbase + s * QK_STG
            + (uint32_t)xrow * 144 + xq * 2;
        uint32_t hw[8], lw[8];
#pragma unroll
        for (int p = 0; p < 8; p++)
            split2(xr[p * 2], xr[p * 2 + 1], hw[p], lw[p]);
        STS128(hw[0], hw[1], hw[2], hw[3], dst + QX_HI);
        STS128(hw[4], hw[5], hw[6], hw[7], dst + QX_HI + 16);
        STS128(lw[0], lw[1], lw[2], lw[3], dst + QX_LO);
        STS128(lw[4], lw[5], lw[6], lw[7], dst + QX_LO + 16);
    };

    auto cpW = [&](int c, int s) {
        const uint32_t base = sbase + s * QK_STG;
#pragma unroll
        for (int t = 0; t < 6; t++) {
            const int i   = tid + t * 512;
            const int arr = (i >= 1536) ? 1 : 0;
            const int i2  = arr ? (i - 1536) : i;
            const int row = i2 >> 3, ch = i2 & 7;
            const __nv_bfloat16* src = (arr ? g_wtlo : g_wthi)
                + (size_t)row * 1024 + c * 64 + ch * 8;
            cp_async16(base + (arr ? QW_LO : QW_HI) + row * 144 + ch * 16, src);
        }
        CP_COMMIT();
    };

    float acc[12][4];
#pragma unroll
    for (int nt = 0; nt < 12; nt++)
#pragma unroll
        for (int e = 0; e < 4; e++) acc[nt][e] = 0.0f;

    ldX(0);
    cpW(0, 0);

    for (int c = 0; c < NCH; c++) {
        const int s = c & 1;
        __syncthreads();
        stX(s);
        if (c + 1 < NCH) {
            cpW(c + 1, s ^ 1);
            asm volatile("cp.async.wait_group 1;" ::: "memory");
        } else {
            asm volatile("cp.async.wait_group 0;" ::: "memory");
        }
        __syncthreads();
        if (c + 1 < NCH) ldX(c + 1);

        const uint32_t xb = sbase + s * QK_STG + QX_HI
            + (uint32_t)(warpM * 16 + (lane & 15)) * 144 + (lane >> 4) * 16;
        const uint32_t wb = sbase + s * QK_STG + QW_HI
            + (uint32_t)(warpN * 96 + ((lane >> 4) & 1) * 8 + (lane & 7)) * 144
            + ((lane >> 3) & 1) * 16;

#pragma unroll
        for (int kc = 0; kc < 4; kc++) {
            uint32_t ah[4], al[4];
            ldsm4(xb + kc * 32, ah);
            ldsm4(xb + (QX_LO - QX_HI) + kc * 32, al);
#pragma unroll
            for (int nt = 0; nt < 6; nt++) {
                uint32_t bh[4], bl[4];
                ldsm4(wb + nt * (16 * 144) + kc * 32, bh);
                ldsm4(wb + (QW_LO - QW_HI) + nt * (16 * 144) + kc * 32, bl);
                mma16816(acc[2 * nt],     ah, bh[0], bh[1]);
                mma16816(acc[2 * nt],     ah, bl[0], bl[1]);
                mma16816(acc[2 * nt],     al, bh[0], bh[1]);
                mma16816(acc[2 * nt + 1], ah, bh[2], bh[3]);
                mma16816(acc[2 * nt + 1], ah, bl[2], bl[3]);
                mma16816(acc[2 * nt + 1], al, bh[2], bh[3]);
            }
        }
    }

    {
        const int rbase = m0 + warpM * 16 + g;
#pragma unroll
        for (int nt = 0; nt < 12; nt++) {
            const int cc = warpN * 96 + nt * 8 + qr * 2;
#pragma unroll
            for (int half = 0; half < 2; half++) {
                const int r = rbase + half * 8;
                float a0 = acc[nt][half * 2 + 0];
                float a1 = acc[nt][half * 2 + 1];
                __nv_bfloat16 *hiA, *loA;
                int col;
                if (cc < 64) {
                    col = cc;
                    a0 = (a0 + bq[col]) * 0.125f;
                    a1 = (a1 + bq[col + 1]) * 0.125f;
                    hiA = g_qhi; loA = g_qlo;
                } else if (cc < 128) {
                    col = cc - 64;
                    a0 += bk[col]; a1 += bk[col + 1];
                    hiA = g_khi; loA = g_klo;
                } else {
                    col = cc - 128;
                    a0 += bv[col]; a1 += bv[col + 1];
                    hiA = g_vhi; loA = g_vlo;
                }
                uint32_t hw, lw;
                split2(a0, a1, hw, lw);
                const size_t idx = (size_t)r * HEAD + col;
                *reinterpret_cast<uint32_t*>(hiA + idx) = hw;
                *reinterpret_cast<uint32_t*>(loA + idx) = lw;
            }
        }
    }
}

// ===========================================================================
// Kernel 2: split-K flash attention. nsp = qt/18 + 1 -> 592 CTAs = 2 waves.
// Full 3-pass emulation on BOTH GEMMs (P-lo pass restored: precision-critical).
// ===========================================================================
#define BQ 64
#define BK 64
#define STRIDE 144

#define SM_QHI   0
#define SM_QLO   9216
#define SM_STAGE 18432
#define STAGE_SZ 36864
#define OFF_KHI  0
#define OFF_KLO  9216
#define OFF_VHI  18432
#define OFF_VLO  27648
#define SM_TOTAL (SM_STAGE + 2 * STAGE_SZ)   // 92160

#define ATTN_GRID (BATCH * 148)              // 592

__global__ __launch_bounds__(128) void attn_mma_kernel(float* __restrict__ out)
{
    extern __shared__ char smem[];
    const uint32_t sbase = smem_u32(smem);

    const int b = blockIdx.x & 3;
    int i = blockIdx.x >> 2;
    int qt = 0, s = i;
#pragma unroll 1
    for (qt = 0; qt < 64; qt++) {
        const int c = qt / 18 + 1;
        if (s < c) break;
        s -= c;
    }
    const int nk  = qt + 1;
    const int nsp = qt / 18 + 1;
    const int chn = (nk + nsp - 1) / nsp;
    const int k0  = s * chn;
    const int k1  = (k0 + chn < nk) ? (k0 + chn) : nk;
    const int q0  = qt * BQ;

    const int tid  = threadIdx.x;
    const int warp = tid >> 5;
    const int lane = tid & 31;
    const int g    = lane >> 2;
    const int qr   = lane & 3;
    const int R    = warp * 16;

    auto prefetch = [&](int kt, int stage) {
        const uint32_t sb = sbase + SM_STAGE + stage * STAGE_SZ;
        const size_t gro = (size_t)(b * SEQ) + (size_t)kt * BK;
#pragma unroll
        for (int t = 0; t < 16; t++) {
            const int ii  = tid + t * 128;
            const int arr = ii >> 9;
            const int rem = ii & 511;
            const int r = rem >> 3, c = rem & 7;
            const __nv_bfloat16* base;
            uint32_t off;
            if (arr == 0)      { base = g_khi; off = OFF_KHI; }
            else if (arr == 1) { base = g_klo; off = OFF_KLO; }
            else if (arr == 2) { base = g_vhi; off = OFF_VHI; }
            else               { base = g_vlo; off = OFF_VLO; }
            cp_async16(sb + off + r * STRIDE + c * 16,
                       base + (gro + r) * HEAD + c * 8);
        }
        CP_COMMIT();
    };

    prefetch(k0, 0);

    for (int ii = tid; ii < 1024; ii += 128) {
        const int arr = ii >> 9;
        const int rem = ii & 511;
        const int r = rem >> 3, c = rem & 7;
        const __nv_bfloat16* src = (arr == 0 ? g_qhi : g_qlo)
            + ((size_t)(b * SEQ) + q0 + r) * HEAD + c * 8;
        const int4 val = *reinterpret_cast<const int4*>(src);
        *reinterpret_cast<int4*>(smem + (arr == 0 ? SM_QHI : SM_QLO)
                                 + r * STRIDE + c * 16) = val;
    }
    __syncthreads();

    const uint32_t aQ = sbase + SM_QHI
        + (uint32_t)(R + (lane & 15)) * STRIDE + ((lane >> 4) * 8) * 2;
    uint32_t qahi[4][4], qalo[4][4];
#pragma unroll
    for (int kc = 0; kc < 4; kc++) {
        ldsm4(aQ + kc * 32, qahi[kc]);
        ldsm4(aQ + 9216 + kc * 32, qalo[kc]);
    }

    const uint32_t oK = (uint32_t)(((lane >> 4) & 1) * 8 + (lane & 7)) * STRIDE
        + (((lane >> 3) & 1) * 8) * 2;
    const uint32_t oV = (uint32_t)(((lane >> 3) & 1) * 8 + (lane & 7)) * STRIDE
        + (((lane >> 4) & 1) * 8) * 2;

    float oacc[8][4];
#pragma unroll
    for (int nt = 0; nt < 8; nt++)
#pragma unroll
        for (int e = 0; e < 4; e++) oacc[nt][e] = 0.0f;
    float mr0 = -1e30f, mr1 = -1e30f, l0 = 0.0f, l1 = 0.0f;

    for (int j = 0; j < k1 - k0; j++) {
        const int kt = k0 + j;
        __syncthreads();
        if (kt + 1 < k1) {
            prefetch(kt + 1, (j + 1) & 1);
            asm volatile("cp.async.wait_group 1;" ::: "memory");
        } else {
            asm volatile("cp.async.wait_group 0;" ::: "memory");
        }
        __syncthreads();

        const uint32_t sb = sbase + SM_STAGE + (j & 1) * STAGE_SZ;
        const uint32_t bK = sb + OFF_KHI + oK;
        const uint32_t bV = sb + OFF_VHI + oV;

        float sacc[8][4];
#pragma unroll
        for (int nt = 0; nt < 8; nt++)
#pragma unroll
            for (int e = 0; e < 4; e++) sacc[nt][e] = 0.0f;

#pragma unroll
        for (int kc = 0; kc < 4; kc++) {
#pragma unroll
            for (int np = 0; np < 4; np++) {
                uint32_t bh[4], bl[4];
                ldsm4(bK + np * (16 * STRIDE) + kc * 32, bh);
                ldsm4(bK + 9216 + np * (16 * STRIDE) + kc * 32, bl);
                mma16816(sacc[2 * np],     qahi[kc], bh[0], bh[1]);
                mma16816(sacc[2 * np],     qahi[kc], bl[0], bl[1]);
                mma16816(sacc[2 * np],     qalo[kc], bh[0], bh[1]);
                mma16816(sacc[2 * np + 1], qahi[kc], bh[2], bh[3]);
                mma16816(sacc[2 * np + 1], qahi[kc], bl[2], bl[3]);
                mma16816(sacc[2 * np + 1], qalo[kc], bh[2], bh[3]);
            }
        }

        if (kt == qt) {
            const int lr0 = R + g, lr1 = R + g + 8;
#pragma unroll
            for (int nt = 0; nt < 8; nt++) {
                const int lc = nt * 8 + qr * 2;
                if (lc > lr0)     sacc[nt][0] = -1e30f;
                if (lc + 1 > lr0) sacc[nt][1] = -1e30f;
                if (lc > lr1)     sacc[nt][2] = -1e30f;
                if (lc + 1 > lr1) sacc[nt][3] = -1e30f;
            }
        }

        float m0 = -1e30f, m1 = -1e30f;
#pragma unroll
        for (int nt = 0; nt < 8; nt++) {
            m0 = fmaxf(m0, fmaxf(sacc[nt][0], sacc[nt][1]));
            m1 = fmaxf(m1, fmaxf(sacc[nt][2], sacc[nt][3]));
        }
        m0 = fmaxf(m0, __shfl_xor_sync(0xffffffffu, m0, 1));
        m0 = fmaxf(m0, __shfl_xor_sync(0xffffffffu, m0, 2));
        m1 = fmaxf(m1, __shfl_xor_sync(0xffffffffu, m1, 1));
        m1 = fmaxf(m1, __shfl_xor_sync(0xffffffffu, m1, 2));

        const float mn0 = fmaxf(mr0, m0);
        const float mn1 = fmaxf(mr1, m1);
        const float corr0 = __expf(mr0 - mn0);
        const float corr1 = __expf(mr1 - mn1);
        mr0 = mn0; mr1 = mn1;

        uint32_t aphi[4][4], aplo[4][4];
        float ps0 = 0.0f, ps1 = 0.0f;
#pragma unroll
        for (int kc2 = 0; kc2 < 4; kc2++) {
            const int ntE = 2 * kc2, ntO = 2 * kc2 + 1;
            float pE0 = __expf(sacc[ntE][0] - mn0);
            float pE1 = __expf(sacc[ntE][1] - mn0);
            float pE2 = __expf(sacc[ntE][2] - mn1);
            float pE3 = __expf(sacc[ntE][3] - mn1);
            float pO0 = __expf(sacc[ntO][0] - mn0);
            float pO1 = __expf(sacc[ntO][1] - mn0);
            float pO2 = __expf(sacc[ntO][2] - mn1);
            float pO3 = __expf(sacc[ntO][3] - mn1);
            ps0 += pE0 + pE1 + pO0 + pO1;
            ps1 += pE2 + pE3 + pO2 + pO3;
            split2(pE0, pE1, aphi[kc2][0], aplo[kc2][0]);
            split2(pE2, pE3, aphi[kc2][1], aplo[kc2][1]);
            split2(pO0, pO1, aphi[kc2][2], aplo[kc2][2]);
            split2(pO2, pO3, aphi[kc2][3], aplo[kc2][3]);
        }
        ps0 += __shfl_xor_sync(0xffffffffu, ps0, 1);
        ps0 += __shfl_xor_sync(0xffffffffu, ps0, 2);
        ps1 += __shfl_xor_sync(0xffffffffu, ps1, 1);
        ps1 += __shfl_xor_sync(0xffffffffu, ps1, 2);
        l0 = l0 * corr0 + ps0;
        l1 = l1 * corr1 + ps1;

#pragma unroll
        for (int nt = 0; nt < 8; nt++) {
            oacc[nt][0] *= corr0; oacc[nt][1] *= corr0;
            oacc[nt][2] *= corr1; oacc[nt][3] *= corr1;
        }

#pragma unroll
        for (int kc2 = 0; kc2 < 4; kc2++) {
#pragma unroll
            for (int np = 0; np < 4; np++) {
                uint32_t bvh[4], bvl[4];
                ldsm4t(bV + kc2 * (16 * STRIDE) + np * 32, bvh);
                ldsm4t(bV + 9216 + kc2 * (16 * STRIDE) + np * 32, bvl);
                mma16816(oacc[2 * np],     aphi[kc2], bvh[0], bvh[1]);
                mma16816(oacc[2 * np],     aphi[kc2], bvl[0], bvl[1]);
                mma16816(oacc[2 * np],     aplo[kc2], bvh[0], bvh[1]);
                mma16816(oacc[2 * np + 1], aphi[kc2], bvh[2], bvh[3]);
                mma16816(oacc[2 * np + 1], aphi[kc2], bvl[2], bvl[3]);
                mma16816(oacc[2 * np + 1], aplo[kc2], bvh[2], bvh[3]);
            }
        }
    }

    // ---- epilogue ----
    if (nsp == 1) {
        const float inv0 = 1.0f / l0;
        const float inv1 = 1.0f / l1;
        const size_t row0 = (size_t)(b * SEQ) + q0 + R + g;
        const size_t row1 = row0 + 8;
#pragma unroll
        for (int nt = 0; nt < 8; nt++) {
            const int col = nt * 8 + qr * 2;
            float2 o0; o0.x = oacc[nt][0] * inv0; o0.y = oacc[nt][1] * inv0;
            float2 o1; o1.x = oacc[nt][2] * inv1; o1.y = oacc[nt][3] * inv1;
            *reinterpret_cast<float2*>(out + row0 * HEAD + col) = o0;
            *reinterpret_cast<float2*>(out + row1 * HEAD + col) = o1;
        }
    } else {
        const int pidx = ((b * 64 + qt) * 4 + s);
        float* op = g_opart + (size_t)pidx * 4096;
#pragma unroll
        for (int nt = 0; nt < 8; nt++) {
            const int col = nt * 8 + qr * 2;
            float2 o0; o0.x = oacc[nt][0]; o0.y = oacc[nt][1];
            float2 o1; o1.x = oacc[nt][2]; o1.y = oacc[nt][3];
            *reinterpret_cast<float2*>(op + (R + g) * 64 + col) = o0;
            *reinterpret_cast<float2*>(op + (R + g + 8) * 64 + col) = o1;
        }
        if (qr == 0) {
            g_mpart[pidx * 64 + R + g]     = mr0;
            g_mpart[pidx * 64 + R + g + 8] = mr1;
            g_lpart[pidx * 64 + R + g]     = l0;
            g_lpart[pidx * 64 + R + g + 8] = l1;
        }
    }
}

// ===========================================================================
// Kernel 3: split-K merge.
// ===========================================================================
__global__ __launch_bounds__(256) void merge_kernel(float* __restrict__ out)
{
    const int b  = blockIdx.x & 3;
    const int qt = blockIdx.x >> 2;
    const int nsp = qt / 18 + 1;
    if (nsp == 1) return;

    const int tid = threadIdx.x;
    const int row = tid >> 2;
    const int cg  = tid & 3;

    const int pbase = (b * 64 + qt) * 4;
    float m[4], lv[4];
    float M = -1e30f;
    for (int s = 0; s < nsp; s++) {
        m[s]  = g_mpart[(pbase + s) * 64 + row];
        lv[s] = g_lpart[(pbase + s) * 64 + row];
        M = fmaxf(M, m[s]);
    }
    float w[4];
    float L = 0.0f;
    for (int s = 0; s < nsp; s++) {
        w[s] = __expf(m[s] - M);
        L += lv[s] * w[s];
    }
    const float inv = 1.0f / L;

    float* o = out + ((size_t)(b * SEQ) + qt * 64 + row) * HEAD + cg * 16;
#pragma unroll
    for (int c4 = 0; c4 < 4; c4++) {
        float4 acc = make_float4(0.f, 0.f, 0.f, 0.f);
        for (int s = 0; s < nsp; s++) {
            const float4 v = *reinterpret_cast<const float4*>(
                g_opart + (size_t)(pbase + s) * 4096 + row * 64 + cg * 16 + c4 * 4);
            acc.x += w[s] * v.x; acc.y += w[s] * v.y;
            acc.z += w[s] * v.z; acc.w += w[s] * v.w;
        }
        acc.x *= inv; acc.y *= inv; acc.z *= inv; acc.w *= inv;
        *reinterpret_cast<float4*>(o + c4 * 4) = acc;
    }
}

// ===========================================================================
extern "C" void kernel_launch(void* const* d_in, const int* in_sizes, int n_in,
                              void* d_out, int out_size)
{
    const float* x  = (const float*)d_in[0];
    const float* Wq = (const float*)d_in[1];
    const float* bq = (const float*)d_in[2];
    const float* Wk = (const float*)d_in[3];
    const float* bk = (const float*)d_in[4];
    const float* Wv = (const float*)d_in[5];
    const float* bv = (const float*)d_in[6];
    float* out = (float*)d_out;

    wconv_kernel<<<48, 256>>>(Wq, Wk, Wv);

    {
        cudaFuncSetAttribute(qkv_mma_kernel,
                             cudaFuncAttributeMaxDynamicSharedMemorySize, QK_SMEM);
        qkv_mma_kernel<<<128, 512, QK_SMEM>>>(x, bq, bk, bv);
    }

    {
        cudaFuncSetAttribute(attn_mma_kernel,
                             cudaFuncAttributeMaxDynamicSharedMemorySize, SM_TOTAL);
        attn_mma_kernel<<<ATTN_GRID, 128, SM_TOTAL>>>(out);
    }

    merge_kernel<<<256, 256>>>(out);
}

// round 11
// speedup vs baseline: 4.9629x; 1.0879x over previous
#include <cuda_runtime.h>
#include <cuda_bf16.h>
#include <math.h>
#include <cstdint>

#define BATCH 4
#define SEQ   4096
#define EMB   1024
#define HEAD  64

// bf16 hi/lo split of projected q (pre-scaled by 0.125*log2e), k, v. 2 MB each.
__device__ __nv_bfloat16 g_qhi[BATCH * SEQ * HEAD];
__device__ __nv_bfloat16 g_qlo[BATCH * SEQ * HEAD];
__device__ __nv_bfloat16 g_khi[BATCH * SEQ * HEAD];
__device__ __nv_bfloat16 g_klo[BATCH * SEQ * HEAD];
__device__ __nv_bfloat16 g_vhi[BATCH * SEQ * HEAD];
__device__ __nv_bfloat16 g_vlo[BATCH * SEQ * HEAD];

// W^T hi/lo: [n=192][k=1024]
__device__ __nv_bfloat16 g_wthi[192 * 1024];
__device__ __nv_bfloat16 g_wtlo[192 * 1024];

// split-K partials: [b][qt][s<=4][64 rows][64 cols] and m/l per row
__device__ float g_opart[BATCH * 64 * 4 * 64 * 64];   // 16 MB
__device__ float g_mpart[BATCH * 64 * 4 * 64];
__device__ float g_lpart[BATCH * 64 * 4 * 64];

// scores arrive pre-scaled by log2(e), so exp2f(s - m) == e^{raw}.
#define QSCALE 0.18033688011112042f   // 0.125 * log2(e)

// ===========================================================================
// helpers
// ===========================================================================
__device__ __forceinline__ uint32_t smem_u32(const void* p) {
    uint32_t a;
    asm("{ .reg .u64 t; cvta.to.shared.u64 t, %1; cvt.u32.u64 %0, t; }"
        : "=r"(a) : "l"(p));
    return a;
}

__device__ __forceinline__ void ldsm4(uint32_t addr, uint32_t* r) {
    asm volatile("ldmatrix.sync.aligned.m8n8.x4.shared.b16 {%0,%1,%2,%3}, [%4];"
        : "=r"(r[0]), "=r"(r[1]), "=r"(r[2]), "=r"(r[3]) : "r"(addr));
}
__device__ __forceinline__ void ldsm4t(uint32_t addr, uint32_t* r) {
    asm volatile("ldmatrix.sync.aligned.m8n8.x4.trans.shared.b16 {%0,%1,%2,%3}, [%4];"
        : "=r"(r[0]), "=r"(r[1]), "=r"(r[2]), "=r"(r[3]) : "r"(addr));
}

__device__ __forceinline__ void mma16816(float* c, const uint32_t* a,
                                         uint32_t b0, uint32_t b1) {
    asm volatile(
        "mma.sync.aligned.m16n8k16.row.col.f32.bf16.bf16.f32 "
        "{%0,%1,%2,%3}, {%4,%5,%6,%7}, {%8,%9}, {%0,%1,%2,%3};"
        : "+f"(c[0]), "+f"(c[1]), "+f"(c[2]), "+f"(c[3])
        : "r"(a[0]), "r"(a[1]), "r"(a[2]), "r"(a[3]), "r"(b0), "r"(b1));
}

__device__ __forceinline__ void cp_async16(uint32_t saddr, const void* gaddr) {
    asm volatile("cp.async.cg.shared.global [%0], [%1], 16;"
        :: "r"(saddr), "l"(gaddr) : "memory");
}
#define CP_COMMIT() asm volatile("cp.async.commit_group;" ::: "memory")

#define STS128(r0, r1, r2, r3, addr) \
    asm volatile("st.shared.v4.b32 [%0], {%1, %2, %3, %4};" \
        :: "r"(addr), "r"(r0), "r"(r1), "r"(r2), "r"(r3) : "memory")

// fast fp32 pair -> bf16 hi word + bf16 lo(residual) word.
// hi via cvt.rn.bf16x2 (same rn rounding as __float2bfloat16);
// hi-as-f32 recovered exactly by 16-bit shifts.
__device__ __forceinline__ void split2(float x0, float x1,
                                       uint32_t& hw, uint32_t& lw) {
    asm("cvt.rn.bf16x2.f32 %0, %1, %2;" : "=r"(hw) : "f"(x1), "f"(x0));
    const float h0 = __uint_as_float(hw << 16);
    const float h1 = __uint_as_float(hw & 0xFFFF0000u);
    const float l0 = x0 - h0;
    const float l1 = x1 - h1;
    asm("cvt.rn.bf16x2.f32 %0, %1, %2;" : "=r"(lw) : "f"(l1), "f"(l0));
}

// ===========================================================================
// Kernel 0: W^T hi/lo precompute (coalesced via smem transpose)
// ===========================================================================
__global__ __launch_bounds__(256) void wconv_kernel(
    const float* __restrict__ Wq, const float* __restrict__ Wk,
    const float* __restrict__ Wv)
{
    __shared__ float tile[64][65];
    const int mat = blockIdx.x >> 4;
    const int k0  = (blockIdx.x & 15) * 64;
    const float* W = (mat == 0) ? Wq : ((mat == 1) ? Wk : Wv);

#pragma unroll
    for (int r = 0; r < 64; r += 4) {
        const int k = k0 + r + (threadIdx.x >> 6);
        const int n = threadIdx.x & 63;
        tile[r + (threadIdx.x >> 6)][n] = W[(size_t)k * 64 + n];
    }
    __syncthreads();

    const int n  = threadIdx.x >> 2;
    const int kc = (threadIdx.x & 3) * 16;
    const size_t base = ((size_t)(mat * 64 + n)) * 1024 + k0 + kc;
#pragma unroll
    for (int j = 0; j < 16; j++) {
        const float v = tile[kc + j][n];
        const __nv_bfloat16 h = __float2bfloat16(v);
        g_wthi[base + j] = h;
        g_wtlo[base + j] = __float2bfloat16(v - __bfloat162float(h));
    }
}

// ===========================================================================
// Kernel 1: QKV projection on mma.sync (3xBF16). 512 threads, 16 warps.
// ===========================================================================
#define QK_STG  92160
#define QX_HI   0
#define QX_LO   18432
#define QW_HI   36864
#define QW_LO   64512
#define QK_SMEM (2 * QK_STG)
#define NCH     (EMB / 64)

__global__ __launch_bounds__(512, 1) void qkv_mma_kernel(
    const float* __restrict__ x,
    const float* __restrict__ bq, const float* __restrict__ bk,
    const float* __restrict__ bv)
{
    extern __shared__ char smem[];
    const uint32_t sbase = smem_u32(smem);
    const int tid  = threadIdx.x;
    const int warp = tid >> 5;
    const int lane = tid & 31;
    const int g    = lane >> 2;
    const int qr   = lane & 3;
    const int warpM = warp >> 1;
    const int warpN = warp & 1;
    const int m0 = blockIdx.x * 128;

    const int xrow = tid >> 2;
    const int xq   = (tid & 3) * 16;

    float xr[16];

    auto ldX = [&](int c) {
        const float4* src = reinterpret_cast<const float4*>(
            x + (size_t)(m0 + xrow) * EMB + c * 64 + xq);
#pragma unroll
        for (int j = 0; j < 4; j++) {
            float4 v = src[j];
            xr[j * 4 + 0] = v.x; xr[j * 4 + 1] = v.y;
            xr[j * 4 + 2] = v.z; xr[j * 4 + 3] = v.w;
        }
    };

    auto stX = [&](int s) {
        const uint32_t dst = sbase + s * QK_STG
            + (uint32_t)xrow * 144 + xq * 2;
        uint32_t hw[8], lw[8];
#pragma unroll
        for (int p = 0; p < 8; p++)
            split2(xr[p * 2], xr[p * 2 + 1], hw[p], lw[p]);
        STS128(hw[0], hw[1], hw[2], hw[3], dst + QX_HI);
        STS128(hw[4], hw[5], hw[6], hw[7], dst + QX_HI + 16);
        STS128(lw[0], lw[1], lw[2], lw[3], dst + QX_LO);
        STS128(lw[4], lw[5], lw[6], lw[7], dst + QX_LO + 16);
    };

    auto cpW = [&](int c, int s) {
        const uint32_t base = sbase + s * QK_STG;
#pragma unroll
        for (int t = 0; t < 6; t++) {
            const int i   = tid + t * 512;
            const int arr = (i >= 1536) ? 1 : 0;
            const int i2  = arr ? (i - 1536) : i;
            const int row = i2 >> 3, ch = i2 & 7;
            const __nv_bfloat16* src = (arr ? g_wtlo : g_wthi)
                + (size_t)row * 1024 + c * 64 + ch * 8;
            cp_async16(base + (arr ? QW_LO : QW_HI) + row * 144 + ch * 16, src);
        }
        CP_COMMIT();
    };

    float acc[12][4];
#pragma unroll
    for (int nt = 0; nt < 12; nt++)
#pragma unroll
        for (int e = 0; e < 4; e++) acc[nt][e] = 0.0f;

    ldX(0);
    cpW(0, 0);

    for (int c = 0; c < NCH; c++) {
        const int s = c & 1;
        __syncthreads();
        stX(s);
        if (c + 1 < NCH) {
            cpW(c + 1, s ^ 1);
            asm volatile("cp.async.wait_group 1;" ::: "memory");
        } else {
            asm volatile("cp.async.wait_group 0;" ::: "memory");
        }
        __syncthreads();
        if (c + 1 < NCH) ldX(c + 1);

        const uint32_t xb = sbase + s * QK_STG + QX_HI
            + (uint32_t)(warpM * 16 + (lane & 15)) * 144 + (lane >> 4) * 16;
        const uint32_t wb = sbase + s * QK_STG + QW_HI
            + (uint32_t)(warpN * 96 + ((lane >> 4) & 1) * 8 + (lane & 7)) * 144
            + ((lane >> 3) & 1) * 16;

#pragma unroll
        for (int kc = 0; kc < 4; kc++) {
            uint32_t ah[4], al[4];
            ldsm4(xb + kc * 32, ah);
            ldsm4(xb + (QX_LO - QX_HI) + kc * 32, al);
#pragma unroll
            for (int nt = 0; nt < 6; nt++) {
                uint32_t bh[4], bl[4];
                ldsm4(wb + nt * (16 * 144) + kc * 32, bh);
                ldsm4(wb + (QW_LO - QW_HI) + nt * (16 * 144) + kc * 32, bl);
                mma16816(acc[2 * nt],     ah, bh[0], bh[1]);
                mma16816(acc[2 * nt],     ah, bl[0], bl[1]);
                mma16816(acc[2 * nt],     al, bh[0], bh[1]);
                mma16816(acc[2 * nt + 1], ah, bh[2], bh[3]);
                mma16816(acc[2 * nt + 1], ah, bl[2], bl[3]);
                mma16816(acc[2 * nt + 1], al, bh[2], bh[3]);
            }
        }
    }

    {
        const int rbase = m0 + warpM * 16 + g;
#pragma unroll
        for (int nt = 0; nt < 12; nt++) {
            const int cc = warpN * 96 + nt * 8 + qr * 2;
#pragma unroll
            for (int half = 0; half < 2; half++) {
                const int r = rbase + half * 8;
                float a0 = acc[nt][half * 2 + 0];
                float a1 = acc[nt][half * 2 + 1];
                __nv_bfloat16 *hiA, *loA;
                int col;
                if (cc < 64) {
                    col = cc;
                    a0 = (a0 + bq[col]) * QSCALE;
                    a1 = (a1 + bq[col + 1]) * QSCALE;
                    hiA = g_qhi; loA = g_qlo;
                } else if (cc < 128) {
                    col = cc - 64;
                    a0 += bk[col]; a1 += bk[col + 1];
                    hiA = g_khi; loA = g_klo;
                } else {
                    col = cc - 128;
                    a0 += bv[col]; a1 += bv[col + 1];
                    hiA = g_vhi; loA = g_vlo;
                }
                uint32_t hw, lw;
                split2(a0, a1, hw, lw);
                const size_t idx = (size_t)r * HEAD + col;
                *reinterpret_cast<uint32_t*>(hiA + idx) = hw;
                *reinterpret_cast<uint32_t*>(loA + idx) = lw;
            }
        }
    }
}

// ===========================================================================
// Kernel 2: split-K flash attention, PV deferred one tile behind S so
// softmax ALU overlaps MMA drain. K prefetch early, V prefetch post-sync.
// ===========================================================================
#define BQ 64
#define BK 64
#define STRIDE 144

#define SM_QHI   0
#define SM_QLO   9216
#define SM_STAGE 18432
#define STAGE_SZ 36864
#define OFF_KHI  0
#define OFF_KLO  9216
#define OFF_VHI  18432
#define OFF_VLO  27648
#define SM_TOTAL (SM_STAGE + 2 * STAGE_SZ)   // 92160

#define ATTN_GRID (BATCH * 148)              // 592 = exactly 2 waves

__global__ __launch_bounds__(128) void attn_mma_kernel(float* __restrict__ out)
{
    extern __shared__ char smem[];
    const uint32_t sbase = smem_u32(smem);

    const int b = blockIdx.x & 3;
    int i = blockIdx.x >> 2;
    int qt = 0, s = i;
#pragma unroll 1
    for (qt = 0; qt < 64; qt++) {
        const int c = qt / 18 + 1;
        if (s < c) break;
        s -= c;
    }
    const int nk  = qt + 1;
    const int nsp = qt / 18 + 1;
    const int chn = (nk + nsp - 1) / nsp;
    const int k0  = s * chn;
    const int k1  = (k0 + chn < nk) ? (k0 + chn) : nk;
    const int cnt = k1 - k0;
    const int q0  = qt * BQ;

    const int tid  = threadIdx.x;
    const int warp = tid >> 5;
    const int lane = tid & 31;
    const int g    = lane >> 2;
    const int qr   = lane & 3;
    const int R    = warp * 16;

    // K half of a stage: khi+klo (1024 16B chunks, 8 per thread)
    auto prefetch_k = [&](int kt, int stage) {
        const uint32_t sb = sbase + SM_STAGE + stage * STAGE_SZ;
        const size_t gro = (size_t)(b * SEQ) + (size_t)kt * BK;
#pragma unroll
        for (int t = 0; t < 8; t++) {
            const int ii  = tid + t * 128;
            const int arr = ii >> 9;
            const int rem = ii & 511;
            const int r = rem >> 3, c = rem & 7;
            const __nv_bfloat16* base = arr ? g_klo : g_khi;
            const uint32_t off = arr ? OFF_KLO : OFF_KHI;
            cp_async16(sb + off + r * STRIDE + c * 16,
                       base + (gro + r) * HEAD + c * 8);
        }
    };
    // V half of a stage
    auto prefetch_v = [&](int kt, int stage) {
        const uint32_t sb = sbase + SM_STAGE + stage * STAGE_SZ;
        const size_t gro = (size_t)(b * SEQ) + (size_t)kt * BK;
#pragma unroll
        for (int t = 0; t < 8; t++) {
            const int ii  = tid + t * 128;
            const int arr = ii >> 9;
            const int rem = ii & 511;
            const int r = rem >> 3, c = rem & 7;
            const __nv_bfloat16* base = arr ? g_vlo : g_vhi;
            const uint32_t off = arr ? OFF_VLO : OFF_VHI;
            cp_async16(sb + off + r * STRIDE + c * 16,
                       base + (gro + r) * HEAD + c * 8);
        }
    };

    // prologue: K group then V group for first tile
    prefetch_k(k0, 0); CP_COMMIT();
    prefetch_v(k0, 0); CP_COMMIT();

    for (int ii = tid; ii < 1024; ii += 128) {
        const int arr = ii >> 9;
        const int rem = ii & 511;
        const int r = rem >> 3, c = rem & 7;
        const __nv_bfloat16* src = (arr == 0 ? g_qhi : g_qlo)
            + ((size_t)(b * SEQ) + q0 + r) * HEAD + c * 8;
        const int4 val = *reinterpret_cast<const int4*>(src);
        *reinterpret_cast<int4*>(smem + (arr == 0 ? SM_QHI : SM_QLO)
                                 + r * STRIDE + c * 16) = val;
    }
    __syncthreads();

    const uint32_t aQ = sbase + SM_QHI
        + (uint32_t)(R + (lane & 15)) * STRIDE + ((lane >> 4) * 8) * 2;
    uint32_t qahi[4][4], qalo[4][4];
#pragma unroll
    for (int kc = 0; kc < 4; kc++) {
        ldsm4(aQ + kc * 32, qahi[kc]);
        ldsm4(aQ + 9216 + kc * 32, qalo[kc]);
    }

    const uint32_t oK = (uint32_t)(((lane >> 4) & 1) * 8 + (lane & 7)) * STRIDE
        + (((lane >> 3) & 1) * 8) * 2;
    const uint32_t oV = (uint32_t)(((lane >> 3) & 1) * 8 + (lane & 7)) * STRIDE
        + (((lane >> 4) & 1) * 8) * 2;

    float oacc[8][4];
#pragma unroll
    for (int nt = 0; nt < 8; nt++)
#pragma unroll
        for (int e = 0; e < 4; e++) oacc[nt][e] = 0.0f;
    float mr0 = -1e30f, mr1 = -1e30f, l0 = 0.0f, l1 = 0.0f;

    // loop-carried P fragments (tile j-1)
    uint32_t aphi[4][4], aplo[4][4];

    for (int j = 0; j < cnt; j++) {
        const int kt = k0 + j;
        // K(j), V(j-1) and older guaranteed done (newest group = V(j))
        asm volatile("cp.async.wait_group 1;" ::: "memory");
        __syncthreads();
        if (j + 1 < cnt) { prefetch_k(kt + 1, (j + 1) & 1); CP_COMMIT(); }

        const uint32_t bK = sbase + SM_STAGE + (j & 1) * STAGE_SZ + OFF_KHI + oK;

        // ---- S(j): 3-pass emulation ----
        float sacc[8][4];
#pragma unroll
        for (int nt = 0; nt < 8; nt++)
#pragma unroll
            for (int e = 0; e < 4; e++) sacc[nt][e] = 0.0f;

#pragma unroll
        for (int kc = 0; kc < 4; kc++) {
#pragma unroll
            for (int np = 0; np < 4; np++) {
                uint32_t bh[4], bl[4];
                ldsm4(bK + np * (16 * STRIDE) + kc * 32, bh);
                ldsm4(bK + 9216 + np * (16 * STRIDE) + kc * 32, bl);
                mma16816(sacc[2 * np],     qahi[kc], bh[0], bh[1]);
                mma16816(sacc[2 * np],     qahi[kc], bl[0], bl[1]);
                mma16816(sacc[2 * np],     qalo[kc], bh[0], bh[1]);
                mma16816(sacc[2 * np + 1], qahi[kc], bh[2], bh[3]);
                mma16816(sacc[2 * np + 1], qahi[kc], bl[2], bl[3]);
                mma16816(sacc[2 * np + 1], qalo[kc], bh[2], bh[3]);
            }
        }

        // ---- PV(j-1): independent of S(j); drains while softmax(j) runs ----
        if (j > 0) {
            const uint32_t bV = sbase + SM_STAGE + ((j & 1) ^ 1) * STAGE_SZ + OFF_VHI + oV;
#pragma unroll
            for (int kc2 = 0; kc2 < 4; kc2++) {
#pragma unroll
                for (int np = 0; np < 4; np++) {
                    uint32_t bvh[4], bvl[4];
                    ldsm4t(bV + kc2 * (16 * STRIDE) + np * 32, bvh);
                    ldsm4t(bV + 9216 + kc2 * (16 * STRIDE) + np * 32, bvl);
                    mma16816(oacc[2 * np],     aphi[kc2], bvh[0], bvh[1]);
                    mma16816(oacc[2 * np],     aphi[kc2], bvl[0], bvl[1]);
                    mma16816(oacc[2 * np],     aplo[kc2], bvh[0], bvh[1]);
                    mma16816(oacc[2 * np + 1], aphi[kc2], bvh[2], bvh[3]);
                    mma16816(oacc[2 * np + 1], aphi[kc2], bvl[2], bvl[3]);
                    mma16816(oacc[2 * np + 1], aplo[kc2], bvh[2], bvh[3]);
                }
            }
        }
        __syncthreads();   // all warps done reading V(j-1) stage
        if (j + 1 < cnt) { prefetch_v(kt + 1, (j + 1) & 1); CP_COMMIT(); }

        // ---- softmax(j) (base-2; scores pre-scaled by log2e) ----
        if (kt == qt) {
            const int lr0 = R + g, lr1 = R + g + 8;
#pragma unroll
            for (int nt = 0; nt < 8; nt++) {
                const int lc = nt * 8 + qr * 2;
                if (lc > lr0)     sacc[nt][0] = -1e30f;
                if (lc + 1 > lr0) sacc[nt][1] = -1e30f;
                if (lc > lr1)     sacc[nt][2] = -1e30f;
                if (lc + 1 > lr1) sacc[nt][3] = -1e30f;
            }
        }

        float m0 = -1e30f, m1 = -1e30f;
#pragma unroll
        for (int nt = 0; nt < 8; nt++) {
            m0 = fmaxf(m0, fmaxf(sacc[nt][0], sacc[nt][1]));
            m1 = fmaxf(m1, fmaxf(sacc[nt][2], sacc[nt][3]));
        }
        m0 = fmaxf(m0, __shfl_xor_sync(0xffffffffu, m0, 1));
        m0 = fmaxf(m0, __shfl_xor_sync(0xffffffffu, m0, 2));
        m1 = fmaxf(m1, __shfl_xor_sync(0xffffffffu, m1, 1));
        m1 = fmaxf(m1, __shfl_xor_sync(0xffffffffu, m1, 2));

        const float mn0 = fmaxf(mr0, m0);
        const float mn1 = fmaxf(mr1, m1);
        const float corr0 = exp2f(mr0 - mn0);
        const float corr1 = exp2f(mr1 - mn1);
        mr0 = mn0; mr1 = mn1;

        float ps0 = 0.0f, ps1 = 0.0f;
#pragma unroll
        for (int kc2 = 0; kc2 < 4; kc2++) {
            const int ntE = 2 * kc2, ntO = 2 * kc2 + 1;
            float pE0 = exp2f(sacc[ntE][0] - mn0);
            float pE1 = exp2f(sacc[ntE][1] - mn0);
            float pE2 = exp2f(sacc[ntE][2] - mn1);
            float pE3 = exp2f(sacc[ntE][3] - mn1);
            float pO0 = exp2f(sacc[ntO][0] - mn0);
            float pO1 = exp2f(sacc[ntO][1] - mn0);
            float pO2 = exp2f(sacc[ntO][2] - mn1);
            float pO3 = exp2f(sacc[ntO][3] - mn1);
            ps0 += pE0 + pE1 + pO0 + pO1;
            ps1 += pE2 + pE3 + pO2 + pO3;
            split2(pE0, pE1, aphi[kc2][0], aplo[kc2][0]);
            split2(pE2, pE3, aphi[kc2][1], aplo[kc2][1]);
            split2(pO0, pO1, aphi[kc2][2], aplo[kc2][2]);
            split2(pO2, pO3, aphi[kc2][3], aplo[kc2][3]);
        }
        ps0 += __shfl_xor_sync(0xffffffffu, ps0, 1);
        ps0 += __shfl_xor_sync(0xffffffffu, ps0, 2);
        ps1 += __shfl_xor_sync(0xffffffffu, ps1, 1);
        ps1 += __shfl_xor_sync(0xffffffffu, ps1, 2);
        l0 = l0 * corr0 + ps0;
        l1 = l1 * corr1 + ps1;

        // rescale AFTER PV(j-1) was folded in (frame m_{j-1} -> m_j)
#pragma unroll
        for (int nt = 0; nt < 8; nt++) {
            oacc[nt][0] *= corr0; oacc[nt][1] *= corr0;
            oacc[nt][2] *= corr1; oacc[nt][3] *= corr1;
        }
    }

    // ---- final PV(cnt-1) ----
    asm volatile("cp.async.wait_group 0;" ::: "memory");
    {
        const uint32_t bV = sbase + SM_STAGE + ((cnt - 1) & 1) * STAGE_SZ + OFF_VHI + oV;
#pragma unroll
        for (int kc2 = 0; kc2 < 4; kc2++) {
#pragma unroll
            for (int np = 0; np < 4; np++) {
                uint32_t bvh[4], bvl[4];
                ldsm4t(bV + kc2 * (16 * STRIDE) + np * 32, bvh);
                ldsm4t(bV + 9216 + kc2 * (16 * STRIDE) + np * 32, bvl);
                mma16816(oacc[2 * np],     aphi[kc2], bvh[0], bvh[1]);
                mma16816(oacc[2 * np],     aphi[kc2], bvl[0], bvl[1]);
                mma16816(oacc[2 * np],     aplo[kc2], bvh[0], bvh[1]);
                mma16816(oacc[2 * np + 1], aphi[kc2], bvh[2], bvh[3]);
                mma16816(oacc[2 * np + 1], aphi[kc2], bvl[2], bvl[3]);
                mma16816(oacc[2 * np + 1], aplo[kc2], bvh[2], bvh[3]);
            }
        }
    }

    // ---- epilogue ----
    if (nsp == 1) {
        const float inv0 = 1.0f / l0;
        const float inv1 = 1.0f / l1;
        const size_t row0 = (size_t)(b * SEQ) + q0 + R + g;
        const size_t row1 = row0 + 8;
#pragma unroll
        for (int nt = 0; nt < 8; nt++) {
            const int col = nt * 8 + qr * 2;
            float2 o0; o0.x = oacc[nt][0] * inv0; o0.y = oacc[nt][1] * inv0;
            float2 o1; o1.x = oacc[nt][2] * inv1; o1.y = oacc[nt][3] * inv1;
            *reinterpret_cast<float2*>(out + row0 * HEAD + col) = o0;
            *reinterpret_cast<float2*>(out + row1 * HEAD + col) = o1;
        }
    } else {
        const int pidx = ((b * 64 + qt) * 4 + s);
        float* op = g_opart + (size_t)pidx * 4096;
#pragma unroll
        for (int nt = 0; nt < 8; nt++) {
            const int col = nt * 8 + qr * 2;
            float2 o0; o0.x = oacc[nt][0]; o0.y = oacc[nt][1];
            float2 o1; o1.x = oacc[nt][2]; o1.y = oacc[nt][3];
            *reinterpret_cast<float2*>(op + (R + g) * 64 + col) = o0;
            *reinterpret_cast<float2*>(op + (R + g + 8) * 64 + col) = o1;
        }
        if (qr == 0) {
            g_mpart[pidx * 64 + R + g]     = mr0;
            g_mpart[pidx * 64 + R + g + 8] = mr1;
            g_lpart[pidx * 64 + R + g]     = l0;
            g_lpart[pidx * 64 + R + g + 8] = l1;
        }
    }
}

// ===========================================================================
// Kernel 3: split-K merge (base-2 weights to match).
// ===========================================================================
__global__ __launch_bounds__(256) void merge_kernel(float* __restrict__ out)
{
    const int b  = blockIdx.x & 3;
    const int qt = blockIdx.x >> 2;
    const int nsp = qt / 18 + 1;
    if (nsp == 1) return;

    const int tid = threadIdx.x;
    const int row = tid >> 2;
    const int cg  = tid & 3;

    const int pbase = (b * 64 + qt) * 4;
    float m[4], lv[4];
    float M = -1e30f;
    for (int s = 0; s < nsp; s++) {
        m[s]  = g_mpart[(pbase + s) * 64 + row];
        lv[s] = g_lpart[(pbase + s) * 64 + row];
        M = fmaxf(M, m[s]);
    }
    float w[4];
    float L = 0.0f;
    for (int s = 0; s < nsp; s++) {
        w[s] = exp2f(m[s] - M);
        L += lv[s] * w[s];
    }
    const float inv = 1.0f / L;

    float* o = out + ((size_t)(b * SEQ) + qt * 64 + row) * HEAD + cg * 16;
#pragma unroll
    for (int c4 = 0; c4 < 4; c4++) {
        float4 acc = make_float4(0.f, 0.f, 0.f, 0.f);
        for (int s = 0; s < nsp; s++) {
            const float4 v = *reinterpret_cast<const float4*>(
                g_opart + (size_t)(pbase + s) * 4096 + row * 64 + cg * 16 + c4 * 4);
            acc.x += w[s] * v.x; acc.y += w[s] * v.y;
            acc.z += w[s] * v.z; acc.w += w[s] * v.w;
        }
        acc.x *= inv; acc.y *= inv; acc.z *= inv; acc.w *= inv;
        *reinterpret_cast<float4*>(o + c4 * 4) = acc;
    }
}

// ===========================================================================
extern "C" void kernel_launch(void* const* d_in, const int* in_sizes, int n_in,
                              void* d_out, int out_size)
{
    const float* x  = (const float*)d_in[0];
    const float* Wq = (const float*)d_in[1];
    const float* bq = (const float*)d_in[2];
    const float* Wk = (const float*)d_in[3];
    const float* bk = (const float*)d_in[4];
    const float* Wv = (const float*)d_in[5];
    const float* bv = (const float*)d_in[6];
    float* out = (float*)d_out;

    wconv_kernel<<<48, 256>>>(Wq, Wk, Wv);

    {
        cudaFuncSetAttribute(qkv_mma_kernel,
                             cudaFuncAttributeMaxDynamicSharedMemorySize, QK_SMEM);
        qkv_mma_kernel<<<128, 512, QK_SMEM>>>(x, bq, bk, bv);
    }

    {
        cudaFuncSetAttribute(attn_mma_kernel,
                             cudaFuncAttributeMaxDynamicSharedMemorySize, SM_TOTAL);
        attn_mma_kernel<<<ATTN_GRID, 128, SM_TOTAL>>>(out);
    }

    merge_kernel<<<256, 256>>>(out);
}